// round 11
// baseline (speedup 1.0000x reference)
#include <cuda_runtime.h>
#include <cstdint>

// ---------------------------------------------------------------------------
// Problem constants
// ---------------------------------------------------------------------------
#define FH 128
#define FW 128
#define NPIX (FH*FW)       // 16384
#define QN 65536           // queries
#define SN (4*QN)          // 262144 corner samples
#define K1 585             // valid unfold dims
#define K0P 608            // padded K for layer0 (mult of 32)
#define NH 256

// ---------------------------------------------------------------------------
// Scratch
// ---------------------------------------------------------------------------
__device__ __align__(128) float g_X[NPIX * K0P];
__device__ __align__(128) float g_Wt0[NH * K0P];
__device__ __align__(128) float g_Wt1[NH * NH];
__device__ __align__(128) float g_Wt2[NH * NH];
__device__ __align__(128) float g_Wt3[NH * NH];
__device__ __align__(128) float g_hp[NPIX * NH];
__device__ __align__(128) float g_pred[SN * 3];

// ---------------------------------------------------------------------------
// PTX helpers (compute_103-portable) — proven
// ---------------------------------------------------------------------------
__device__ __forceinline__ uint32_t smem_u32(const void* p) {
    uint32_t a;
    asm("{ .reg .u64 t; cvta.to.shared.u64 t, %1; cvt.u32.u64 %0, t; }" : "=r"(a) : "l"(p));
    return a;
}
__device__ __forceinline__ float rnd_tf32(float x) {
    uint32_t r;
    asm("cvt.rna.tf32.f32 %0, %1;" : "=r"(r) : "f"(x));
    return __uint_as_float(r);
}
__device__ __forceinline__ void cp16(uint32_t dst, const void* src) {
    asm volatile("cp.async.cg.shared.global [%0], [%1], 16;" :: "r"(dst), "l"(src));
}
#define CP_COMMIT() asm volatile("cp.async.commit_group;" ::: "memory")
#define CP_WAIT(n)  asm volatile("cp.async.wait_group %0;" :: "n"(n) : "memory")

__device__ __forceinline__ void ldsm4(uint32_t* r, uint32_t addr) {
    asm volatile("ldmatrix.sync.aligned.m8n8.x4.shared.b16 {%0,%1,%2,%3}, [%4];"
                 : "=r"(r[0]), "=r"(r[1]), "=r"(r[2]), "=r"(r[3]) : "r"(addr));
}
__device__ __forceinline__ void mma_tf32(float* d, const uint32_t* a, const uint32_t* b) {
    asm volatile(
        "mma.sync.aligned.m16n8k8.row.col.f32.tf32.tf32.f32 "
        "{%0,%1,%2,%3}, {%4,%5,%6,%7}, {%8,%9}, {%0,%1,%2,%3};"
        : "+f"(d[0]), "+f"(d[1]), "+f"(d[2]), "+f"(d[3])
        : "r"(a[0]), "r"(a[1]), "r"(a[2]), "r"(a[3]), "r"(b[0]), "r"(b[1]));
}

// stage format: rows x 128B, chunk-XOR swizzle (proven)
__device__ __forceinline__ uint32_t swzo(int r, int c) {
    return (uint32_t)(r * 128 + ((c ^ (r & 7)) << 4));
}

// ---------------------------------------------------------------------------
// Standalone GEMM for layer 0 (R8-proven): 3-stage, BM=128, BN=128, 256 thr
// ---------------------------------------------------------------------------
#define AST 16384
#define NST 3
#define B_BASE3 (NST * AST)
#define SMEM_GEMM (2 * NST * AST)

__device__ __forceinline__ void load_A3(uint32_t sb, const float* __restrict__ A,
                                        size_t bm, int k0, int stg, int K, int tid) {
    uint32_t ab = sb + stg * AST;
#pragma unroll
    for (int i = 0; i < 4; i++) {
        int li = tid + i * 256;
        int m = li >> 3, c = li & 7;
        cp16(ab + swzo(m, c), A + (bm + m) * (size_t)K + k0 + c * 4);
    }
}
__device__ __forceinline__ void load_B3(uint32_t sb, const float* __restrict__ Bt,
                                        int bn, int k0, int stg, int K, int tid) {
    uint32_t bb = sb + B_BASE3 + stg * AST;
#pragma unroll
    for (int i = 0; i < 4; i++) {
        int li = tid + i * 256;
        int n = li >> 3, c = li & 7;
        cp16(bb + swzo(n, c), Bt + (size_t)(bn + n) * K + k0 + c * 4);
    }
}

__global__ __launch_bounds__(256, 2) void gemm_l0(const float* __restrict__ A,
                                                  const float* __restrict__ Bt,
                                                  const float* __restrict__ bias,
                                                  float* __restrict__ C, int K) {
    extern __shared__ char smem[];
    uint32_t sb = smem_u32(smem);
    const int tid = threadIdx.x;
    const int wid = tid >> 5, lane = tid & 31;
    const int wm = wid >> 2, wn = wid & 3;
    const size_t bm = (size_t)blockIdx.y * 128;
    const int bn = blockIdx.x * 128;
    const int nit = K >> 5;

    float acc[4][4][4];
#pragma unroll
    for (int i = 0; i < 4; i++)
#pragma unroll
        for (int j = 0; j < 4; j++)
#pragma unroll
            for (int v = 0; v < 4; v++) acc[i][j][v] = 0.f;

    load_A3(sb, A, bm, 0, 0, K, tid);  load_B3(sb, Bt, bn, 0, 0, K, tid);  CP_COMMIT();
    load_A3(sb, A, bm, 32, 1, K, tid); load_B3(sb, Bt, bn, 32, 1, K, tid); CP_COMMIT();

    const int rw = lane & 7;
    const int j  = lane >> 3;
    const int a_r = wm * 64 + rw + (j & 1) * 8;
    const int a_c = j >> 1;
    const int b_r = wn * 32 + rw + (j >> 1) * 8;
    const int b_c = j & 1;

    for (int it = 0; it < nit; it++) {
        if (it + 1 < nit) { CP_WAIT(1); } else { CP_WAIT(0); }
        __syncthreads();
        if (it + 2 < nit) {
            int stg = (it + 2) % NST;
            load_A3(sb, A, bm, (it + 2) * 32, stg, K, tid);
            load_B3(sb, Bt, bn, (it + 2) * 32, stg, K, tid);
            CP_COMMIT();
        }
        int stg = it % NST;
        uint32_t abase = sb + stg * AST;
        uint32_t bbase = sb + B_BASE3 + stg * AST;
#pragma unroll
        for (int ks = 0; ks < 4; ks++) {
            uint32_t afr[4][4];
#pragma unroll
            for (int mt = 0; mt < 4; mt++)
                ldsm4(afr[mt], abase + swzo(a_r + mt * 16, ks * 2 + a_c));
            uint32_t bfr[2][4];
#pragma unroll
            for (int gg = 0; gg < 2; gg++)
                ldsm4(bfr[gg], bbase + swzo(b_r + gg * 16, ks * 2 + b_c));
#pragma unroll
            for (int mt = 0; mt < 4; mt++)
#pragma unroll
                for (int nt = 0; nt < 4; nt++)
                    mma_tf32(acc[mt][nt], afr[mt], &bfr[nt >> 1][(nt & 1) * 2]);
        }
    }

    const int er = lane >> 2;
    const int ec = (lane & 3) * 2;
#pragma unroll
    for (int mt = 0; mt < 4; mt++) {
#pragma unroll
        for (int nt = 0; nt < 4; nt++) {
            int n = bn + wn * 32 + nt * 8 + ec;
            float bi0 = __ldg(&bias[n]);
            float bi1 = __ldg(&bias[n + 1]);
            size_t m0 = bm + wm * 64 + mt * 16 + er;
            *reinterpret_cast<float2*>(&C[m0 * 256 + n]) =
                make_float2(acc[mt][nt][0] + bi0, acc[mt][nt][1] + bi1);
            *reinterpret_cast<float2*>(&C[(m0 + 8) * 256 + n]) =
                make_float2(acc[mt][nt][2] + bi0, acc[mt][nt][3] + bi1);
        }
    }
}

// ---------------------------------------------------------------------------
// Corner geometry (proven)
// ---------------------------------------------------------------------------
__device__ __forceinline__ void corner_calc(float c0, float c1, int cc,
                                            int& idx, float& rel0, float& rel1) {
    const float rr = 1.0f / 128.0f;
    float vx = (cc & 2) ? 1.f : -1.f;
    float vy = (cc & 1) ? 1.f : -1.f;
    float cy = fminf(fmaxf(c0 + vx * rr + 1e-6f, -1.f + 1e-6f), 1.f - 1e-6f);
    float cx = fminf(fmaxf(c1 + vy * rr + 1e-6f, -1.f + 1e-6f), 1.f - 1e-6f);
    int iy = (int)rintf(((cy + 1.0f) * 128.0f - 1.0f) * 0.5f);
    int ix = (int)rintf(((cx + 1.0f) * 128.0f - 1.0f) * 0.5f);
    iy = min(max(iy, 0), 127);
    ix = min(max(ix, 0), 127);
    float qy = -1.0f + (2.0f * (float)iy + 1.0f) / 128.0f;
    float qx = -1.0f + (2.0f * (float)ix + 1.0f) / 128.0f;
    rel0 = (c0 - qy) * 128.0f;
    rel1 = (c1 - qx) * 128.0f;
    idx = iy * 128 + ix;
}

// ---------------------------------------------------------------------------
// Megakernel: layers 1-3 fused. BM=128 samples/CTA, BN=256, 512 threads.
// h (128x256 f32) resident in 8 swizzled 16KB panels.
// B: 3-stage (32KB each), single barrier per K-iteration (R8-proven pattern).
// idx/r0/r1 overlay B stage 0 during prologue fill (separated by barrier).
// W4 read via __ldg in the final epilogue (no smem needed).
// ---------------------------------------------------------------------------
#define H_PANELS 8
#define MK_B_BASE (H_PANELS * AST)          // 131072
#define MK_B_STG  32768                      // 256 rows x 128B
#define SMEM_MK   (MK_B_BASE + 3 * MK_B_STG) // 229376
#define MK_T 512

__device__ __forceinline__ void mk_load_B(uint32_t sb, const float* __restrict__ Bt,
                                          int k0, int stg, int tid) {
    uint32_t bb = sb + MK_B_BASE + stg * MK_B_STG;
#pragma unroll
    for (int i = 0; i < 4; i++) {
        int li = tid + i * MK_T;             // 0..2047
        int n = li >> 3, c = li & 7;
        cp16(bb + swzo(n, c), Bt + (size_t)n * 256 + k0 + c * 4);
    }
}

__global__ __launch_bounds__(MK_T) void mk_layers(const float* __restrict__ hr,
                                                  const float* __restrict__ W0,
                                                  const float* __restrict__ Bt1,
                                                  const float* __restrict__ b1,
                                                  const float* __restrict__ Bt2,
                                                  const float* __restrict__ b2,
                                                  const float* __restrict__ Bt3,
                                                  const float* __restrict__ b3,
                                                  const float* __restrict__ W4) {
    extern __shared__ char smem[];
    uint32_t sb = smem_u32(smem);
    // overlay (valid only until first B load; separated by __syncthreads)
    int*   sIdx = (int*)(smem + MK_B_BASE);
    float* sR0  = (float*)(smem + MK_B_BASE + 512);
    float* sR1  = (float*)(smem + MK_B_BASE + 1024);

    const int tid = threadIdx.x;
    const int wid = tid >> 5, lane = tid & 31;
    const int wm = wid >> 2;            // 0..3 (32-row blocks)
    const int wn = wid & 3;             // 0..3 (64-col blocks)
    const size_t bm = (size_t)blockIdx.x * 128;
    const int er = lane >> 2;
    const int ec = (lane & 3) * 2;

    if (tid < 128) {
        size_t s = bm + tid;
        int cc = (int)(s >> 16);
        int q  = (int)(s & 65535);
        float c0 = hr[2 * q], c1 = hr[2 * q + 1];
        int idx; float r0, r1;
        corner_calc(c0, c1, cc, idx, r0, r1);
        sIdx[tid] = idx; sR0[tid] = r0; sR1[tid] = r1;
    }
    __syncthreads();

    // ---- fill h = rnd(relu(hp[idx] + r0*W0[585] + r1*W0[586])) (hp has b0) ----
#pragma unroll
    for (int p = 0; p < H_PANELS; p++) {
        int k0 = p * 32;
#pragma unroll
        for (int i = 0; i < 2; i++) {
            int li = tid + i * MK_T;         // 0..1023
            int m = li >> 3, c = li & 7;
            int row = sIdx[m];
            float r0 = sR0[m], r1 = sR1[m];
            float4 h  = __ldg((const float4*)&g_hp[(size_t)row * 256 + k0 + c * 4]);
            float4 wa = __ldg((const float4*)&W0[585 * 256 + k0 + c * 4]);
            float4 wb = __ldg((const float4*)&W0[586 * 256 + k0 + c * 4]);
            float4 o;
            o.x = rnd_tf32(fmaxf(h.x + r0 * wa.x + r1 * wb.x, 0.f));
            o.y = rnd_tf32(fmaxf(h.y + r0 * wa.y + r1 * wb.y, 0.f));
            o.z = rnd_tf32(fmaxf(h.z + r0 * wa.z + r1 * wb.z, 0.f));
            o.w = rnd_tf32(fmaxf(h.w + r0 * wa.w + r1 * wb.w, 0.f));
            *reinterpret_cast<float4*>(smem + p * AST + swzo(m, c)) = o;
        }
    }
    __syncthreads();   // fill done; idx overlay dead; B loads may begin

    const int rw = lane & 7;
    const int jq = lane >> 3;
    const int a_r = wm * 32 + rw + (jq & 1) * 8;
    const int a_c = jq >> 1;
    const int b_r = wn * 64 + rw + (jq >> 1) * 8;
    const int b_c = jq & 1;

    const float* Bts[3]    = {Bt1, Bt2, Bt3};
    const float* biases[3] = {b1, b2, b3};

#pragma unroll 1
    for (int L = 0; L < 3; L++) {
        const float* Bt = Bts[L];
        const float* bias = biases[L];

        float acc[2][8][4];
#pragma unroll
        for (int i = 0; i < 2; i++)
#pragma unroll
            for (int j = 0; j < 8; j++)
#pragma unroll
                for (int v = 0; v < 4; v++) acc[i][j][v] = 0.f;

        mk_load_B(sb, Bt, 0, 0, tid);  CP_COMMIT();
        mk_load_B(sb, Bt, 32, 1, tid); CP_COMMIT();

#pragma unroll 1
        for (int it = 0; it < 8; it++) {
            if (it + 1 < 8) { CP_WAIT(1); } else { CP_WAIT(0); }
            __syncthreads();
            // prefetch stage it+2 (consumed at it-1; barrier above protects it)
            if (it + 2 < 8) {
                mk_load_B(sb, Bt, (it + 2) * 32, (it + 2) % 3, tid);
                CP_COMMIT();
            }
            uint32_t abase = sb + it * AST;
            uint32_t bbase = sb + MK_B_BASE + (it % 3) * MK_B_STG;
#pragma unroll
            for (int ks = 0; ks < 4; ks++) {
                uint32_t afr[2][4];
#pragma unroll
                for (int mt = 0; mt < 2; mt++)
                    ldsm4(afr[mt], abase + swzo(a_r + mt * 16, ks * 2 + a_c));
                uint32_t bfr[4][4];
#pragma unroll
                for (int gg = 0; gg < 4; gg++)
                    ldsm4(bfr[gg], bbase + swzo(b_r + gg * 16, ks * 2 + b_c));
#pragma unroll
                for (int mt = 0; mt < 2; mt++)
#pragma unroll
                    for (int nt = 0; nt < 8; nt++)
                        mma_tf32(acc[mt][nt], afr[mt], &bfr[nt >> 1][(nt & 1) * 2]);
            }
        }
        __syncthreads();   // all mma reads of h and B stages complete

        if (L < 2) {
            // write acc -> h panels with bias+relu+rnd
#pragma unroll
            for (int mt = 0; mt < 2; mt++) {
#pragma unroll
                for (int nt = 0; nt < 8; nt++) {
                    int n = wn * 64 + nt * 8 + ec;
                    float bi0 = __ldg(&bias[n]);
                    float bi1 = __ldg(&bias[n + 1]);
                    int r0 = wm * 32 + mt * 16 + er;
                    int r1 = r0 + 8;
                    float v0 = rnd_tf32(fmaxf(acc[mt][nt][0] + bi0, 0.f));
                    float v1 = rnd_tf32(fmaxf(acc[mt][nt][1] + bi1, 0.f));
                    float v2 = rnd_tf32(fmaxf(acc[mt][nt][2] + bi0, 0.f));
                    float v3 = rnd_tf32(fmaxf(acc[mt][nt][3] + bi1, 0.f));
                    int panel = n >> 5;
                    int chunk = (n & 31) >> 2;
                    int sub = (n & 3) * 4;
                    *reinterpret_cast<float2*>(smem + panel * AST + r0 * 128 +
                                               ((chunk ^ (r0 & 7)) << 4) + sub) =
                        make_float2(v0, v1);
                    *reinterpret_cast<float2*>(smem + panel * AST + r1 * 128 +
                                               ((chunk ^ (r1 & 7)) << 4) + sub) =
                        make_float2(v2, v3);
                }
            }
            __syncthreads();
        } else {
            // fused final layer: h4 = relu(acc + b3); dot with W4 (__ldg); atomics
#pragma unroll
            for (int mt = 0; mt < 2; mt++) {
                float p[2][3];
#pragma unroll
                for (int h = 0; h < 2; h++)
#pragma unroll
                    for (int c = 0; c < 3; c++) p[h][c] = 0.f;
#pragma unroll
                for (int nt = 0; nt < 8; nt++) {
                    int n = wn * 64 + nt * 8 + ec;
                    float bi0 = __ldg(&bias[n]);
                    float bi1 = __ldg(&bias[n + 1]);
                    float v0 = fmaxf(acc[mt][nt][0] + bi0, 0.f);
                    float v1 = fmaxf(acc[mt][nt][1] + bi1, 0.f);
                    float v2 = fmaxf(acc[mt][nt][2] + bi0, 0.f);
                    float v3 = fmaxf(acc[mt][nt][3] + bi1, 0.f);
#pragma unroll
                    for (int c = 0; c < 3; c++) {
                        float w0 = __ldg(&W4[n * 3 + c]);
                        float w1 = __ldg(&W4[(n + 1) * 3 + c]);
                        p[0][c] += v0 * w0 + v1 * w1;
                        p[1][c] += v2 * w0 + v3 * w1;
                    }
                }
#pragma unroll
                for (int h = 0; h < 2; h++)
#pragma unroll
                    for (int c = 0; c < 3; c++) {
                        p[h][c] += __shfl_xor_sync(0xFFFFFFFFu, p[h][c], 1);
                        p[h][c] += __shfl_xor_sync(0xFFFFFFFFu, p[h][c], 2);
                    }
                if ((lane & 3) == 0) {
                    size_t m0 = bm + wm * 32 + mt * 16 + er;
#pragma unroll
                    for (int c = 0; c < 3; c++) {
                        atomicAdd(&g_pred[m0 * 3 + c],       p[0][c]);
                        atomicAdd(&g_pred[(m0 + 8) * 3 + c], p[1][c]);
                    }
                }
            }
        }
    }
}

// ---------------------------------------------------------------------------
// im2col (padded, tf32-rounded)
// ---------------------------------------------------------------------------
__global__ void build_X(const float* __restrict__ mf, const float* __restrict__ mask) {
    int p = blockIdx.x;
    int t = threadIdx.x;
    if (t >= K0P) return;
    int y = p >> 7, x = p & 127;
    float v = 0.f;
    if (t < K1) {
        int c = t / 9, r = t - c * 9;
        int ki = r / 3, kj = r - ki * 3;
        int yy = y + ki - 1, xx = x + kj - 1;
        if (yy >= 0 && yy < FH && xx >= 0 && xx < FW) {
            v = (c < 64) ? mf[(c << 14) + (yy << 7) + xx] : mask[(yy << 7) + xx];
        }
        v = rnd_tf32(v);
    }
    g_X[p * K0P + t] = v;
}

// ---------------------------------------------------------------------------
// Merged prep: transpose+round all 4 weights + zero g_pred, one launch
// ---------------------------------------------------------------------------
#define SEG0 (256 * K0P)
#define SEG1 (256 * 256)
#define PREP_TOT (SEG0 + 3 * SEG1 + SN * 3)
__global__ void prep_all(const float* __restrict__ W0, const float* __restrict__ W1,
                         const float* __restrict__ W2, const float* __restrict__ W3) {
    int i = blockIdx.x * blockDim.x + threadIdx.x;
    if (i >= PREP_TOT) return;
    if (i < SEG0) {
        int n = i / K0P, k = i - n * K0P;
        g_Wt0[i] = (k < K1) ? rnd_tf32(W0[k * 256 + n]) : 0.f;
        return;
    }
    i -= SEG0;
    if (i < SEG1) { int n = i >> 8, k = i & 255; g_Wt1[i] = rnd_tf32(W1[k * 256 + n]); return; }
    i -= SEG1;
    if (i < SEG1) { int n = i >> 8, k = i & 255; g_Wt2[i] = rnd_tf32(W2[k * 256 + n]); return; }
    i -= SEG1;
    if (i < SEG1) { int n = i >> 8, k = i & 255; g_Wt3[i] = rnd_tf32(W3[k * 256 + n]); return; }
    i -= SEG1;
    g_pred[i] = 0.f;
}

// ---------------------------------------------------------------------------
// local ensemble (adds b4)
// ---------------------------------------------------------------------------
__global__ void ensemble(const float* __restrict__ hr, const float* __restrict__ b4,
                         float* __restrict__ out) {
    int q = blockIdx.x * blockDim.x + threadIdx.x;
    if (q >= QN) return;
    float c0 = hr[2 * q], c1 = hr[2 * q + 1];
    float b40 = __ldg(&b4[0]), b41 = __ldg(&b4[1]), b42 = __ldg(&b4[2]);
    float area[4];
#pragma unroll
    for (int cc = 0; cc < 4; cc++) {
        int idx; float r0, r1;
        corner_calc(c0, c1, cc, idx, r0, r1);
        area[cc] = fabsf(r0 * r1) + 1e-9f;
    }
    float tot = area[0] + area[1] + area[2] + area[3];
    float o0 = 0.f, o1 = 0.f, o2 = 0.f;
#pragma unroll
    for (int cc = 0; cc < 4; cc++) {
        float w = area[3 - cc] / tot;
        size_t s = (size_t)cc * QN + q;
        o0 += (g_pred[s * 3 + 0] + b40) * w;
        o1 += (g_pred[s * 3 + 1] + b41) * w;
        o2 += (g_pred[s * 3 + 2] + b42) * w;
    }
    out[0 * QN + q] = o0;
    out[1 * QN + q] = o1;
    out[2 * QN + q] = o2;
}

// ---------------------------------------------------------------------------
// Launch
// ---------------------------------------------------------------------------
extern "C" void kernel_launch(void* const* d_in, const int* in_sizes, int n_in,
                              void* d_out, int out_size) {
    const float* mf   = (const float*)d_in[0];
    const float* mask = (const float*)d_in[1];
    const float* hr = (const float*)d_in[3];
    const float* W0 = (const float*)d_in[4];
    const float* b0 = (const float*)d_in[5];
    const float* W1 = (const float*)d_in[6];
    const float* b1 = (const float*)d_in[7];
    const float* W2 = (const float*)d_in[8];
    const float* b2 = (const float*)d_in[9];
    const float* W3 = (const float*)d_in[10];
    const float* b3 = (const float*)d_in[11];
    const float* W4 = (const float*)d_in[12];
    const float* b4 = (const float*)d_in[13];
    float* out = (float*)d_out;

    void *pX, *pWt0, *pWt1, *pWt2, *pWt3, *pHp;
    cudaGetSymbolAddress(&pX,   g_X);
    cudaGetSymbolAddress(&pWt0, g_Wt0);
    cudaGetSymbolAddress(&pWt1, g_Wt1);
    cudaGetSymbolAddress(&pWt2, g_Wt2);
    cudaGetSymbolAddress(&pWt3, g_Wt3);
    cudaGetSymbolAddress(&pHp,  g_hp);

    cudaFuncSetAttribute(gemm_l0,   cudaFuncAttributeMaxDynamicSharedMemorySize, SMEM_GEMM);
    cudaFuncSetAttribute(mk_layers, cudaFuncAttributeMaxDynamicSharedMemorySize, SMEM_MK);

    build_X<<<NPIX, 640>>>(mf, mask);
    prep_all<<<(PREP_TOT + 255) / 256, 256>>>(W0, W1, W2, W3);

    // hp = X @ W0 + b0
    gemm_l0<<<dim3(2, NPIX / 128), 256, SMEM_GEMM>>>((const float*)pX, (const float*)pWt0,
                                                     b0, (float*)pHp, K0P);

    // layers 1-3 fused (512 threads, 3-stage B, single barrier per iter)
    mk_layers<<<SN / 128, MK_T, SMEM_MK>>>(hr, W0,
                                           (const float*)pWt1, b1,
                                           (const float*)pWt2, b2,
                                           (const float*)pWt3, b3, W4);

    ensemble<<<QN / 256, 256>>>(hr, b4, out);
}

// round 12
// speedup vs baseline: 1.6594x; 1.6594x over previous
#include <cuda_runtime.h>
#include <cuda_fp16.h>
#include <cstdint>

// ---------------------------------------------------------------------------
// Problem constants
// ---------------------------------------------------------------------------
#define FH 128
#define FW 128
#define NPIX (FH*FW)       // 16384
#define QN 65536           // queries
#define SN (4*QN)          // 262144 corner samples
#define K1 585             // valid unfold dims
#define K0P 608            // padded K for layer0 (mult of 32)
#define NH 256

// ---------------------------------------------------------------------------
// Scratch
// ---------------------------------------------------------------------------
__device__ __align__(128) float  g_X[NPIX * K0P];
__device__ __align__(128) float  g_Wt0[NH * K0P];      // tf32 layer-0 weights
__device__ __align__(128) __half g_Wth1[NH * NH];      // fp16 transposed weights
__device__ __align__(128) __half g_Wth2[NH * NH];
__device__ __align__(128) __half g_Wth3[NH * NH];
__device__ __align__(128) float  g_hp[NPIX * NH];
__device__ __align__(128) float  g_pred[SN * 3];

// ---------------------------------------------------------------------------
// PTX helpers (compute_103-portable) — proven
// ---------------------------------------------------------------------------
__device__ __forceinline__ uint32_t smem_u32(const void* p) {
    uint32_t a;
    asm("{ .reg .u64 t; cvta.to.shared.u64 t, %1; cvt.u32.u64 %0, t; }" : "=r"(a) : "l"(p));
    return a;
}
__device__ __forceinline__ float rnd_tf32(float x) {
    uint32_t r;
    asm("cvt.rna.tf32.f32 %0, %1;" : "=r"(r) : "f"(x));
    return __uint_as_float(r);
}
__device__ __forceinline__ void cp16(uint32_t dst, const void* src) {
    asm volatile("cp.async.cg.shared.global [%0], [%1], 16;" :: "r"(dst), "l"(src));
}
#define CP_COMMIT() asm volatile("cp.async.commit_group;" ::: "memory")
#define CP_WAIT(n)  asm volatile("cp.async.wait_group %0;" :: "n"(n) : "memory")

__device__ __forceinline__ void ldsm4(uint32_t* r, uint32_t addr) {
    asm volatile("ldmatrix.sync.aligned.m8n8.x4.shared.b16 {%0,%1,%2,%3}, [%4];"
                 : "=r"(r[0]), "=r"(r[1]), "=r"(r[2]), "=r"(r[3]) : "r"(addr));
}
__device__ __forceinline__ void mma_tf32(float* d, const uint32_t* a, const uint32_t* b) {
    asm volatile(
        "mma.sync.aligned.m16n8k8.row.col.f32.tf32.tf32.f32 "
        "{%0,%1,%2,%3}, {%4,%5,%6,%7}, {%8,%9}, {%0,%1,%2,%3};"
        : "+f"(d[0]), "+f"(d[1]), "+f"(d[2]), "+f"(d[3])
        : "r"(a[0]), "r"(a[1]), "r"(a[2]), "r"(a[3]), "r"(b[0]), "r"(b[1]));
}
__device__ __forceinline__ void mma_f16(float* d, const uint32_t* a, const uint32_t* b) {
    asm volatile(
        "mma.sync.aligned.m16n8k16.row.col.f32.f16.f16.f32 "
        "{%0,%1,%2,%3}, {%4,%5,%6,%7}, {%8,%9}, {%0,%1,%2,%3};"
        : "+f"(d[0]), "+f"(d[1]), "+f"(d[2]), "+f"(d[3])
        : "r"(a[0]), "r"(a[1]), "r"(a[2]), "r"(a[3]), "r"(b[0]), "r"(b[1]));
}

// stage format: rows x 128B, chunk-XOR swizzle (proven)
__device__ __forceinline__ uint32_t swzo(int r, int c) {
    return (uint32_t)(r * 128 + ((c ^ (r & 7)) << 4));
}

// ---------------------------------------------------------------------------
// Standalone tf32 GEMM for layer 0 (R8/R10-proven): 3-stage, BM=128, BN=128
// ---------------------------------------------------------------------------
#define AST 16384
#define NST 3
#define B_BASE3 (NST * AST)
#define SMEM_GEMM (2 * NST * AST)

__device__ __forceinline__ void load_A3(uint32_t sb, const float* __restrict__ A,
                                        size_t bm, int k0, int stg, int K, int tid) {
    uint32_t ab = sb + stg * AST;
#pragma unroll
    for (int i = 0; i < 4; i++) {
        int li = tid + i * 256;
        int m = li >> 3, c = li & 7;
        cp16(ab + swzo(m, c), A + (bm + m) * (size_t)K + k0 + c * 4);
    }
}
__device__ __forceinline__ void load_B3(uint32_t sb, const float* __restrict__ Bt,
                                        int bn, int k0, int stg, int K, int tid) {
    uint32_t bb = sb + B_BASE3 + stg * AST;
#pragma unroll
    for (int i = 0; i < 4; i++) {
        int li = tid + i * 256;
        int n = li >> 3, c = li & 7;
        cp16(bb + swzo(n, c), Bt + (size_t)(bn + n) * K + k0 + c * 4);
    }
}

__global__ __launch_bounds__(256, 2) void gemm_l0(const float* __restrict__ A,
                                                  const float* __restrict__ Bt,
                                                  const float* __restrict__ bias,
                                                  float* __restrict__ C, int K) {
    extern __shared__ char smem[];
    uint32_t sb = smem_u32(smem);
    const int tid = threadIdx.x;
    const int wid = tid >> 5, lane = tid & 31;
    const int wm = wid >> 2, wn = wid & 3;
    const size_t bm = (size_t)blockIdx.y * 128;
    const int bn = blockIdx.x * 128;
    const int nit = K >> 5;

    float acc[4][4][4];
#pragma unroll
    for (int i = 0; i < 4; i++)
#pragma unroll
        for (int j = 0; j < 4; j++)
#pragma unroll
            for (int v = 0; v < 4; v++) acc[i][j][v] = 0.f;

    load_A3(sb, A, bm, 0, 0, K, tid);  load_B3(sb, Bt, bn, 0, 0, K, tid);  CP_COMMIT();
    load_A3(sb, A, bm, 32, 1, K, tid); load_B3(sb, Bt, bn, 32, 1, K, tid); CP_COMMIT();

    const int rw = lane & 7;
    const int j  = lane >> 3;
    const int a_r = wm * 64 + rw + (j & 1) * 8;
    const int a_c = j >> 1;
    const int b_r = wn * 32 + rw + (j >> 1) * 8;
    const int b_c = j & 1;

    for (int it = 0; it < nit; it++) {
        if (it + 1 < nit) { CP_WAIT(1); } else { CP_WAIT(0); }
        __syncthreads();
        if (it + 2 < nit) {
            int stg = (it + 2) % NST;
            load_A3(sb, A, bm, (it + 2) * 32, stg, K, tid);
            load_B3(sb, Bt, bn, (it + 2) * 32, stg, K, tid);
            CP_COMMIT();
        }
        int stg = it % NST;
        uint32_t abase = sb + stg * AST;
        uint32_t bbase = sb + B_BASE3 + stg * AST;
#pragma unroll
        for (int ks = 0; ks < 4; ks++) {
            uint32_t afr[4][4];
#pragma unroll
            for (int mt = 0; mt < 4; mt++)
                ldsm4(afr[mt], abase + swzo(a_r + mt * 16, ks * 2 + a_c));
            uint32_t bfr[2][4];
#pragma unroll
            for (int gg = 0; gg < 2; gg++)
                ldsm4(bfr[gg], bbase + swzo(b_r + gg * 16, ks * 2 + b_c));
#pragma unroll
            for (int mt = 0; mt < 4; mt++)
#pragma unroll
                for (int nt = 0; nt < 4; nt++)
                    mma_tf32(acc[mt][nt], afr[mt], &bfr[nt >> 1][(nt & 1) * 2]);
        }
    }

    const int er = lane >> 2;
    const int ec = (lane & 3) * 2;
#pragma unroll
    for (int mt = 0; mt < 4; mt++) {
#pragma unroll
        for (int nt = 0; nt < 4; nt++) {
            int n = bn + wn * 32 + nt * 8 + ec;
            float bi0 = __ldg(&bias[n]);
            float bi1 = __ldg(&bias[n + 1]);
            size_t m0 = bm + wm * 64 + mt * 16 + er;
            *reinterpret_cast<float2*>(&C[m0 * 256 + n]) =
                make_float2(acc[mt][nt][0] + bi0, acc[mt][nt][1] + bi1);
            *reinterpret_cast<float2*>(&C[(m0 + 8) * 256 + n]) =
                make_float2(acc[mt][nt][2] + bi0, acc[mt][nt][3] + bi1);
        }
    }
}

// ---------------------------------------------------------------------------
// Corner geometry (proven)
// ---------------------------------------------------------------------------
__device__ __forceinline__ void corner_calc(float c0, float c1, int cc,
                                            int& idx, float& rel0, float& rel1) {
    const float rr = 1.0f / 128.0f;
    float vx = (cc & 2) ? 1.f : -1.f;
    float vy = (cc & 1) ? 1.f : -1.f;
    float cy = fminf(fmaxf(c0 + vx * rr + 1e-6f, -1.f + 1e-6f), 1.f - 1e-6f);
    float cx = fminf(fmaxf(c1 + vy * rr + 1e-6f, -1.f + 1e-6f), 1.f - 1e-6f);
    int iy = (int)rintf(((cy + 1.0f) * 128.0f - 1.0f) * 0.5f);
    int ix = (int)rintf(((cx + 1.0f) * 128.0f - 1.0f) * 0.5f);
    iy = min(max(iy, 0), 127);
    ix = min(max(ix, 0), 127);
    float qy = -1.0f + (2.0f * (float)iy + 1.0f) / 128.0f;
    float qx = -1.0f + (2.0f * (float)ix + 1.0f) / 128.0f;
    rel0 = (c0 - qy) * 128.0f;
    rel1 = (c1 - qx) * 128.0f;
    idx = iy * 128 + ix;
}

// ---------------------------------------------------------------------------
// fp16 megakernel: layers 1-3 fused. BM=128 samples/CTA, BN=256, 512 threads.
// h (128x256 f16) resident in 4 swizzled 16KB panels (128B rows = 64 halves).
// B: fp16, BK=64, 2-stage x 32KB, R10-proven dual-sync loop (nit=4).
// Warps 4(m) x 4(n), warp tile 32x64 (m16n8k16). Final layer fused.
// ---------------------------------------------------------------------------
#define HP_AST 16384                          // one h panel (128 rows x 128B)
#define HPN 4
#define MKF_B_BASE (HPN * HP_AST)             // 65536
#define MKF_B_STG  32768                      // 256 rows x 128B
#define MKF_IDX    (MKF_B_BASE + 2 * MKF_B_STG)  // 131072
#define SMEM_MKF   (MKF_IDX + 1536)           // 132608
#define MK_T 512

__device__ __forceinline__ void mkf_load_B(uint32_t sb, const __half* __restrict__ Bt,
                                           int k0, int stg, int tid) {
    uint32_t bb = sb + MKF_B_BASE + stg * MKF_B_STG;
#pragma unroll
    for (int i = 0; i < 4; i++) {
        int li = tid + i * MK_T;              // 0..2047
        int n = li >> 3, c = li & 7;          // row, 16B chunk (8 halves)
        cp16(bb + swzo(n, c), Bt + (size_t)n * 256 + k0 + c * 8);
    }
}

__global__ __launch_bounds__(MK_T) void mk_layers(const float* __restrict__ hr,
                                                  const float* __restrict__ W0,
                                                  const __half* __restrict__ Bt1,
                                                  const float* __restrict__ b1,
                                                  const __half* __restrict__ Bt2,
                                                  const float* __restrict__ b2,
                                                  const __half* __restrict__ Bt3,
                                                  const float* __restrict__ b3,
                                                  const float* __restrict__ W4) {
    extern __shared__ char smem[];
    uint32_t sb = smem_u32(smem);
    int*   sIdx = (int*)(smem + MKF_IDX);
    float* sR0  = (float*)(smem + MKF_IDX + 512);
    float* sR1  = (float*)(smem + MKF_IDX + 1024);

    const int tid = threadIdx.x;
    const int wid = tid >> 5, lane = tid & 31;
    const int wm = wid >> 2;            // 0..3 (32-row blocks)
    const int wn = wid & 3;             // 0..3 (64-col blocks)
    const size_t bm = (size_t)blockIdx.x * 128;
    const int er = lane >> 2;
    const int ec = (lane & 3) * 2;

    if (tid < 128) {
        size_t s = bm + tid;
        int cc = (int)(s >> 16);
        int q  = (int)(s & 65535);
        float c0 = hr[2 * q], c1 = hr[2 * q + 1];
        int idx; float r0, r1;
        corner_calc(c0, c1, cc, idx, r0, r1);
        sIdx[tid] = idx; sR0[tid] = r0; sR1[tid] = r1;
    }
    __syncthreads();

    // ---- fill h(f16) = h16(relu(hp[idx] + r0*W0[585] + r1*W0[586])) ----
#pragma unroll
    for (int p = 0; p < HPN; p++) {
        int kbase = p * 64;
#pragma unroll
        for (int i = 0; i < 2; i++) {
            int li = tid + i * MK_T;         // 0..1023
            int m = li >> 3, c = li & 7;     // row, 16B chunk (8 halves)
            int k = kbase + c * 8;
            int row = sIdx[m];
            float r0 = sR0[m], r1 = sR1[m];
            float4 h0  = __ldg((const float4*)&g_hp[(size_t)row * 256 + k]);
            float4 h1  = __ldg((const float4*)&g_hp[(size_t)row * 256 + k + 4]);
            float4 wa0 = __ldg((const float4*)&W0[585 * 256 + k]);
            float4 wa1 = __ldg((const float4*)&W0[585 * 256 + k + 4]);
            float4 wb0 = __ldg((const float4*)&W0[586 * 256 + k]);
            float4 wb1 = __ldg((const float4*)&W0[586 * 256 + k + 4]);
            __half2 x0 = __floats2half2_rn(fmaxf(h0.x + r0 * wa0.x + r1 * wb0.x, 0.f),
                                           fmaxf(h0.y + r0 * wa0.y + r1 * wb0.y, 0.f));
            __half2 x1 = __floats2half2_rn(fmaxf(h0.z + r0 * wa0.z + r1 * wb0.z, 0.f),
                                           fmaxf(h0.w + r0 * wa0.w + r1 * wb0.w, 0.f));
            __half2 x2 = __floats2half2_rn(fmaxf(h1.x + r0 * wa1.x + r1 * wb1.x, 0.f),
                                           fmaxf(h1.y + r0 * wa1.y + r1 * wb1.y, 0.f));
            __half2 x3 = __floats2half2_rn(fmaxf(h1.z + r0 * wa1.z + r1 * wb1.z, 0.f),
                                           fmaxf(h1.w + r0 * wa1.w + r1 * wb1.w, 0.f));
            uint4 o;
            o.x = *reinterpret_cast<uint32_t*>(&x0);
            o.y = *reinterpret_cast<uint32_t*>(&x1);
            o.z = *reinterpret_cast<uint32_t*>(&x2);
            o.w = *reinterpret_cast<uint32_t*>(&x3);
            *reinterpret_cast<uint4*>(smem + p * HP_AST + swzo(m, c)) = o;
        }
    }
    __syncthreads();

    // ldmatrix geometry (fp16 k16): A quads {m,k0-7},{m+8,k0-7},{m,k8-15},{m+8,k8-15}
    const int rw = lane & 7;
    const int jq = lane >> 3;
    const int a_r = wm * 32 + rw + (jq & 1) * 8;
    const int a_c = jq >> 1;
    const int b_r = wn * 64 + rw + (jq >> 1) * 8;
    const int b_c = jq & 1;

    const __half* Bts[3]   = {Bt1, Bt2, Bt3};
    const float* biases[3] = {b1, b2, b3};

#pragma unroll 1
    for (int L = 0; L < 3; L++) {
        const __half* Bt = Bts[L];
        const float* bias = biases[L];

        float acc[2][8][4];
#pragma unroll
        for (int i = 0; i < 2; i++)
#pragma unroll
            for (int j = 0; j < 8; j++)
#pragma unroll
                for (int v = 0; v < 4; v++) acc[i][j][v] = 0.f;

        mkf_load_B(sb, Bt, 0, 0, tid);  CP_COMMIT();
        mkf_load_B(sb, Bt, 64, 1, tid); CP_COMMIT();

#pragma unroll 1
        for (int it = 0; it < 4; it++) {
            if (it + 1 < 4) { CP_WAIT(1); } else { CP_WAIT(0); }
            __syncthreads();
            uint32_t abase = sb + it * HP_AST;          // panel it == K chunk it
            uint32_t bbase = sb + MKF_B_BASE + (it & 1) * MKF_B_STG;
#pragma unroll
            for (int ks = 0; ks < 4; ks++) {            // four k16 steps per BK=64
                int cb = ks * 2;
                uint32_t afr[2][4];
#pragma unroll
                for (int mt = 0; mt < 2; mt++)
                    ldsm4(afr[mt], abase + swzo(a_r + mt * 16, cb + a_c));
                uint32_t bfr[4][4];
#pragma unroll
                for (int gg = 0; gg < 4; gg++)
                    ldsm4(bfr[gg], bbase + swzo(b_r + gg * 16, cb + b_c));
#pragma unroll
                for (int mt = 0; mt < 2; mt++)
#pragma unroll
                    for (int nt = 0; nt < 8; nt++)
                        mma_f16(acc[mt][nt], afr[mt], &bfr[nt >> 1][(nt & 1) * 2]);
            }
            __syncthreads();
            if (it + 2 < 4) {
                mkf_load_B(sb, Bt, (it + 2) * 64, it & 1, tid);
                CP_COMMIT();
            }
        }

        if (L < 2) {
            // write acc -> h panels (f16) with bias+relu
#pragma unroll
            for (int mt = 0; mt < 2; mt++) {
#pragma unroll
                for (int nt = 0; nt < 8; nt++) {
                    int n = wn * 64 + nt * 8 + ec;
                    float bi0 = __ldg(&bias[n]);
                    float bi1 = __ldg(&bias[n + 1]);
                    int r0 = wm * 32 + mt * 16 + er;
                    int r1 = r0 + 8;
                    __half2 lo = __floats2half2_rn(fmaxf(acc[mt][nt][0] + bi0, 0.f),
                                                   fmaxf(acc[mt][nt][1] + bi1, 0.f));
                    __half2 hi = __floats2half2_rn(fmaxf(acc[mt][nt][2] + bi0, 0.f),
                                                   fmaxf(acc[mt][nt][3] + bi1, 0.f));
                    int panel = n >> 6;
                    int chunk = (n & 63) >> 3;
                    int sub = (n & 7) * 2;               // 0,4,8,12 (ec even)
                    *reinterpret_cast<__half2*>(smem + panel * HP_AST +
                                                swzo(r0, chunk) + sub) = lo;
                    *reinterpret_cast<__half2*>(smem + panel * HP_AST +
                                                swzo(r1, chunk) + sub) = hi;
                }
            }
            __syncthreads();
        } else {
            // fused final layer: h4 = relu(acc + b3); dot with W4 (__ldg); atomics
#pragma unroll
            for (int mt = 0; mt < 2; mt++) {
                float p[2][3];
#pragma unroll
                for (int h = 0; h < 2; h++)
#pragma unroll
                    for (int c = 0; c < 3; c++) p[h][c] = 0.f;
#pragma unroll
                for (int nt = 0; nt < 8; nt++) {
                    int n = wn * 64 + nt * 8 + ec;
                    float bi0 = __ldg(&bias[n]);
                    float bi1 = __ldg(&bias[n + 1]);
                    float v0 = fmaxf(acc[mt][nt][0] + bi0, 0.f);
                    float v1 = fmaxf(acc[mt][nt][1] + bi1, 0.f);
                    float v2 = fmaxf(acc[mt][nt][2] + bi0, 0.f);
                    float v3 = fmaxf(acc[mt][nt][3] + bi1, 0.f);
#pragma unroll
                    for (int c = 0; c < 3; c++) {
                        float w0 = __ldg(&W4[n * 3 + c]);
                        float w1 = __ldg(&W4[(n + 1) * 3 + c]);
                        p[0][c] += v0 * w0 + v1 * w1;
                        p[1][c] += v2 * w0 + v3 * w1;
                    }
                }
#pragma unroll
                for (int h = 0; h < 2; h++)
#pragma unroll
                    for (int c = 0; c < 3; c++) {
                        p[h][c] += __shfl_xor_sync(0xFFFFFFFFu, p[h][c], 1);
                        p[h][c] += __shfl_xor_sync(0xFFFFFFFFu, p[h][c], 2);
                    }
                if ((lane & 3) == 0) {
                    size_t m0 = bm + wm * 32 + mt * 16 + er;
#pragma unroll
                    for (int c = 0; c < 3; c++) {
                        atomicAdd(&g_pred[m0 * 3 + c],       p[0][c]);
                        atomicAdd(&g_pred[(m0 + 8) * 3 + c], p[1][c]);
                    }
                }
            }
        }
    }
}

// ---------------------------------------------------------------------------
// im2col (padded, tf32-rounded)
// ---------------------------------------------------------------------------
__global__ void build_X(const float* __restrict__ mf, const float* __restrict__ mask) {
    int p = blockIdx.x;
    int t = threadIdx.x;
    if (t >= K0P) return;
    int y = p >> 7, x = p & 127;
    float v = 0.f;
    if (t < K1) {
        int c = t / 9, r = t - c * 9;
        int ki = r / 3, kj = r - ki * 3;
        int yy = y + ki - 1, xx = x + kj - 1;
        if (yy >= 0 && yy < FH && xx >= 0 && xx < FW) {
            v = (c < 64) ? mf[(c << 14) + (yy << 7) + xx] : mask[(yy << 7) + xx];
        }
        v = rnd_tf32(v);
    }
    g_X[p * K0P + t] = v;
}

// ---------------------------------------------------------------------------
// Merged prep: Wt0 (tf32) + Wt1..3 (fp16 transposed) + zero g_pred
// ---------------------------------------------------------------------------
#define SEG0 (256 * K0P)
#define SEG1 (256 * 256)
#define PREP_TOT (SEG0 + 3 * SEG1 + SN * 3)
__global__ void prep_all(const float* __restrict__ W0, const float* __restrict__ W1,
                         const float* __restrict__ W2, const float* __restrict__ W3) {
    int i = blockIdx.x * blockDim.x + threadIdx.x;
    if (i >= PREP_TOT) return;
    if (i < SEG0) {
        int n = i / K0P, k = i - n * K0P;
        g_Wt0[i] = (k < K1) ? rnd_tf32(W0[k * 256 + n]) : 0.f;
        return;
    }
    i -= SEG0;
    if (i < SEG1) { int n = i >> 8, k = i & 255; g_Wth1[i] = __float2half_rn(W1[k * 256 + n]); return; }
    i -= SEG1;
    if (i < SEG1) { int n = i >> 8, k = i & 255; g_Wth2[i] = __float2half_rn(W2[k * 256 + n]); return; }
    i -= SEG1;
    if (i < SEG1) { int n = i >> 8, k = i & 255; g_Wth3[i] = __float2half_rn(W3[k * 256 + n]); return; }
    i -= SEG1;
    g_pred[i] = 0.f;
}

// ---------------------------------------------------------------------------
// local ensemble (adds b4)
// ---------------------------------------------------------------------------
__global__ void ensemble(const float* __restrict__ hr, const float* __restrict__ b4,
                         float* __restrict__ out) {
    int q = blockIdx.x * blockDim.x + threadIdx.x;
    if (q >= QN) return;
    float c0 = hr[2 * q], c1 = hr[2 * q + 1];
    float b40 = __ldg(&b4[0]), b41 = __ldg(&b4[1]), b42 = __ldg(&b4[2]);
    float area[4];
#pragma unroll
    for (int cc = 0; cc < 4; cc++) {
        int idx; float r0, r1;
        corner_calc(c0, c1, cc, idx, r0, r1);
        area[cc] = fabsf(r0 * r1) + 1e-9f;
    }
    float tot = area[0] + area[1] + area[2] + area[3];
    float o0 = 0.f, o1 = 0.f, o2 = 0.f;
#pragma unroll
    for (int cc = 0; cc < 4; cc++) {
        float w = area[3 - cc] / tot;
        size_t s = (size_t)cc * QN + q;
        o0 += (g_pred[s * 3 + 0] + b40) * w;
        o1 += (g_pred[s * 3 + 1] + b41) * w;
        o2 += (g_pred[s * 3 + 2] + b42) * w;
    }
    out[0 * QN + q] = o0;
    out[1 * QN + q] = o1;
    out[2 * QN + q] = o2;
}

// ---------------------------------------------------------------------------
// Launch
// ---------------------------------------------------------------------------
extern "C" void kernel_launch(void* const* d_in, const int* in_sizes, int n_in,
                              void* d_out, int out_size) {
    const float* mf   = (const float*)d_in[0];
    const float* mask = (const float*)d_in[1];
    const float* hr = (const float*)d_in[3];
    const float* W0 = (const float*)d_in[4];
    const float* b0 = (const float*)d_in[5];
    const float* W1 = (const float*)d_in[6];
    const float* b1 = (const float*)d_in[7];
    const float* W2 = (const float*)d_in[8];
    const float* b2 = (const float*)d_in[9];
    const float* W3 = (const float*)d_in[10];
    const float* b3 = (const float*)d_in[11];
    const float* W4 = (const float*)d_in[12];
    const float* b4 = (const float*)d_in[13];
    float* out = (float*)d_out;

    void *pX, *pWt0, *pW1, *pW2, *pW3, *pHp;
    cudaGetSymbolAddress(&pX,   g_X);
    cudaGetSymbolAddress(&pWt0, g_Wt0);
    cudaGetSymbolAddress(&pW1,  g_Wth1);
    cudaGetSymbolAddress(&pW2,  g_Wth2);
    cudaGetSymbolAddress(&pW3,  g_Wth3);
    cudaGetSymbolAddress(&pHp,  g_hp);

    cudaFuncSetAttribute(gemm_l0,   cudaFuncAttributeMaxDynamicSharedMemorySize, SMEM_GEMM);
    cudaFuncSetAttribute(mk_layers, cudaFuncAttributeMaxDynamicSharedMemorySize, SMEM_MKF);

    build_X<<<NPIX, 640>>>(mf, mask);
    prep_all<<<(PREP_TOT + 255) / 256, 256>>>(W0, W1, W2, W3);

    // hp = X @ W0 + b0 (tf32, proven)
    gemm_l0<<<dim3(2, NPIX / 128), 256, SMEM_GEMM>>>((const float*)pX, (const float*)pWt0,
                                                     b0, (float*)pHp, K0P);

    // layers 1-3 fused, fp16 mainloop (512 threads, BK=64, 2-stage dual-sync)
    mk_layers<<<SN / 128, MK_T, SMEM_MKF>>>(hr, W0,
                                            (const __half*)pW1, b1,
                                            (const __half*)pW2, b2,
                                            (const __half*)pW3, b3, W4);

    ensemble<<<QN / 256, 256>>>(hr, b4, out);
}

// round 13
// speedup vs baseline: 1.6776x; 1.0110x over previous
#include <cuda_runtime.h>
#include <cuda_fp16.h>
#include <cstdint>

// ---------------------------------------------------------------------------
// Problem constants
// ---------------------------------------------------------------------------
#define FH 128
#define FW 128
#define NPIX (FH*FW)       // 16384
#define QN 65536           // queries
#define SN (4*QN)          // 262144 corner samples
#define K1 585             // valid unfold dims
#define K0P 608            // padded K for layer0 (mult of 32)
#define NH 256

// ---------------------------------------------------------------------------
// Scratch
// ---------------------------------------------------------------------------
__device__ __align__(128) float  g_X[NPIX * K0P];
__device__ __align__(128) float  g_Wt0[NH * K0P];      // tf32 layer-0 weights
__device__ __align__(128) __half g_Wth1[NH * NH];      // fp16 transposed weights
__device__ __align__(128) __half g_Wth2[NH * NH];
__device__ __align__(128) __half g_Wth3[NH * NH];
__device__ __align__(128) float  g_hp[NPIX * NH];
__device__ __align__(128) float  g_pred[SN * 3];

// ---------------------------------------------------------------------------
// PTX helpers (compute_103-portable) — proven
// ---------------------------------------------------------------------------
__device__ __forceinline__ uint32_t smem_u32(const void* p) {
    uint32_t a;
    asm("{ .reg .u64 t; cvta.to.shared.u64 t, %1; cvt.u32.u64 %0, t; }" : "=r"(a) : "l"(p));
    return a;
}
__device__ __forceinline__ float rnd_tf32(float x) {
    uint32_t r;
    asm("cvt.rna.tf32.f32 %0, %1;" : "=r"(r) : "f"(x));
    return __uint_as_float(r);
}
__device__ __forceinline__ void cp16(uint32_t dst, const void* src) {
    asm volatile("cp.async.cg.shared.global [%0], [%1], 16;" :: "r"(dst), "l"(src));
}
#define CP_COMMIT() asm volatile("cp.async.commit_group;" ::: "memory")
#define CP_WAIT(n)  asm volatile("cp.async.wait_group %0;" :: "n"(n) : "memory")

__device__ __forceinline__ void ldsm4(uint32_t* r, uint32_t addr) {
    asm volatile("ldmatrix.sync.aligned.m8n8.x4.shared.b16 {%0,%1,%2,%3}, [%4];"
                 : "=r"(r[0]), "=r"(r[1]), "=r"(r[2]), "=r"(r[3]) : "r"(addr));
}
__device__ __forceinline__ void mma_tf32(float* d, const uint32_t* a, const uint32_t* b) {
    asm volatile(
        "mma.sync.aligned.m16n8k8.row.col.f32.tf32.tf32.f32 "
        "{%0,%1,%2,%3}, {%4,%5,%6,%7}, {%8,%9}, {%0,%1,%2,%3};"
        : "+f"(d[0]), "+f"(d[1]), "+f"(d[2]), "+f"(d[3])
        : "r"(a[0]), "r"(a[1]), "r"(a[2]), "r"(a[3]), "r"(b[0]), "r"(b[1]));
}
__device__ __forceinline__ void mma_f16(float* d, const uint32_t* a, const uint32_t* b) {
    asm volatile(
        "mma.sync.aligned.m16n8k16.row.col.f32.f16.f16.f32 "
        "{%0,%1,%2,%3}, {%4,%5,%6,%7}, {%8,%9}, {%0,%1,%2,%3};"
        : "+f"(d[0]), "+f"(d[1]), "+f"(d[2]), "+f"(d[3])
        : "r"(a[0]), "r"(a[1]), "r"(a[2]), "r"(a[3]), "r"(b[0]), "r"(b[1]));
}

// stage format: rows x 128B, chunk-XOR swizzle (proven)
__device__ __forceinline__ uint32_t swzo(int r, int c) {
    return (uint32_t)(r * 128 + ((c ^ (r & 7)) << 4));
}

// ---------------------------------------------------------------------------
// Standalone tf32 GEMM for layer 0 (R8/R10-proven): 3-stage, BM=128, BN=128
// ---------------------------------------------------------------------------
#define AST 16384
#define NST 3
#define B_BASE3 (NST * AST)
#define SMEM_GEMM (2 * NST * AST)

__device__ __forceinline__ void load_A3(uint32_t sb, const float* __restrict__ A,
                                        size_t bm, int k0, int stg, int K, int tid) {
    uint32_t ab = sb + stg * AST;
#pragma unroll
    for (int i = 0; i < 4; i++) {
        int li = tid + i * 256;
        int m = li >> 3, c = li & 7;
        cp16(ab + swzo(m, c), A + (bm + m) * (size_t)K + k0 + c * 4);
    }
}
__device__ __forceinline__ void load_B3(uint32_t sb, const float* __restrict__ Bt,
                                        int bn, int k0, int stg, int K, int tid) {
    uint32_t bb = sb + B_BASE3 + stg * AST;
#pragma unroll
    for (int i = 0; i < 4; i++) {
        int li = tid + i * 256;
        int n = li >> 3, c = li & 7;
        cp16(bb + swzo(n, c), Bt + (size_t)(bn + n) * K + k0 + c * 4);
    }
}

__global__ __launch_bounds__(256, 2) void gemm_l0(const float* __restrict__ A,
                                                  const float* __restrict__ Bt,
                                                  const float* __restrict__ bias,
                                                  float* __restrict__ C, int K) {
    extern __shared__ char smem[];
    uint32_t sb = smem_u32(smem);
    const int tid = threadIdx.x;
    const int wid = tid >> 5, lane = tid & 31;
    const int wm = wid >> 2, wn = wid & 3;
    const size_t bm = (size_t)blockIdx.y * 128;
    const int bn = blockIdx.x * 128;
    const int nit = K >> 5;

    float acc[4][4][4];
#pragma unroll
    for (int i = 0; i < 4; i++)
#pragma unroll
        for (int j = 0; j < 4; j++)
#pragma unroll
            for (int v = 0; v < 4; v++) acc[i][j][v] = 0.f;

    load_A3(sb, A, bm, 0, 0, K, tid);  load_B3(sb, Bt, bn, 0, 0, K, tid);  CP_COMMIT();
    load_A3(sb, A, bm, 32, 1, K, tid); load_B3(sb, Bt, bn, 32, 1, K, tid); CP_COMMIT();

    const int rw = lane & 7;
    const int j  = lane >> 3;
    const int a_r = wm * 64 + rw + (j & 1) * 8;
    const int a_c = j >> 1;
    const int b_r = wn * 32 + rw + (j >> 1) * 8;
    const int b_c = j & 1;

    for (int it = 0; it < nit; it++) {
        if (it + 1 < nit) { CP_WAIT(1); } else { CP_WAIT(0); }
        __syncthreads();
        if (it + 2 < nit) {
            int stg = (it + 2) % NST;
            load_A3(sb, A, bm, (it + 2) * 32, stg, K, tid);
            load_B3(sb, Bt, bn, (it + 2) * 32, stg, K, tid);
            CP_COMMIT();
        }
        int stg = it % NST;
        uint32_t abase = sb + stg * AST;
        uint32_t bbase = sb + B_BASE3 + stg * AST;
#pragma unroll
        for (int ks = 0; ks < 4; ks++) {
            uint32_t afr[4][4];
#pragma unroll
            for (int mt = 0; mt < 4; mt++)
                ldsm4(afr[mt], abase + swzo(a_r + mt * 16, ks * 2 + a_c));
            uint32_t bfr[2][4];
#pragma unroll
            for (int gg = 0; gg < 2; gg++)
                ldsm4(bfr[gg], bbase + swzo(b_r + gg * 16, ks * 2 + b_c));
#pragma unroll
            for (int mt = 0; mt < 4; mt++)
#pragma unroll
                for (int nt = 0; nt < 4; nt++)
                    mma_tf32(acc[mt][nt], afr[mt], &bfr[nt >> 1][(nt & 1) * 2]);
        }
    }

    const int er = lane >> 2;
    const int ec = (lane & 3) * 2;
#pragma unroll
    for (int mt = 0; mt < 4; mt++) {
#pragma unroll
        for (int nt = 0; nt < 4; nt++) {
            int n = bn + wn * 32 + nt * 8 + ec;
            float bi0 = __ldg(&bias[n]);
            float bi1 = __ldg(&bias[n + 1]);
            size_t m0 = bm + wm * 64 + mt * 16 + er;
            *reinterpret_cast<float2*>(&C[m0 * 256 + n]) =
                make_float2(acc[mt][nt][0] + bi0, acc[mt][nt][1] + bi1);
            *reinterpret_cast<float2*>(&C[(m0 + 8) * 256 + n]) =
                make_float2(acc[mt][nt][2] + bi0, acc[mt][nt][3] + bi1);
        }
    }
}

// ---------------------------------------------------------------------------
// Corner geometry (proven)
// ---------------------------------------------------------------------------
__device__ __forceinline__ void corner_calc(float c0, float c1, int cc,
                                            int& idx, float& rel0, float& rel1) {
    const float rr = 1.0f / 128.0f;
    float vx = (cc & 2) ? 1.f : -1.f;
    float vy = (cc & 1) ? 1.f : -1.f;
    float cy = fminf(fmaxf(c0 + vx * rr + 1e-6f, -1.f + 1e-6f), 1.f - 1e-6f);
    float cx = fminf(fmaxf(c1 + vy * rr + 1e-6f, -1.f + 1e-6f), 1.f - 1e-6f);
    int iy = (int)rintf(((cy + 1.0f) * 128.0f - 1.0f) * 0.5f);
    int ix = (int)rintf(((cx + 1.0f) * 128.0f - 1.0f) * 0.5f);
    iy = min(max(iy, 0), 127);
    ix = min(max(ix, 0), 127);
    float qy = -1.0f + (2.0f * (float)iy + 1.0f) / 128.0f;
    float qx = -1.0f + (2.0f * (float)ix + 1.0f) / 128.0f;
    rel0 = (c0 - qy) * 128.0f;
    rel1 = (c1 - qx) * 128.0f;
    idx = iy * 128 + ix;
}

// ---------------------------------------------------------------------------
// fp16 megakernel: layers 1-3 fused. BM=64 samples/CTA, BN=256, 512 threads,
// 2 CTAs/SM (64 regs/thread). h (64x256 f16) in 4 swizzled 8KB panels.
// B: fp16, BK=64, 2-stage x 32KB, R12-proven dual-sync loop (nit=4).
// Warps 2(m) x 8(n), warp tile 32x32 (m16n8k16). Final layer fused.
// ---------------------------------------------------------------------------
#define HP_AST 8192                           // one h panel (64 rows x 128B)
#define HPN 4
#define MKF_B_BASE (HPN * HP_AST)             // 32768
#define MKF_B_STG  32768                      // 256 rows x 128B
#define MKF_IDX    (MKF_B_BASE + 2 * MKF_B_STG)  // 98304
#define SMEM_MKF   (MKF_IDX + 768)            // 99072
#define MK_T 512

__device__ __forceinline__ void mkf_load_B(uint32_t sb, const __half* __restrict__ Bt,
                                           int k0, int stg, int tid) {
    uint32_t bb = sb + MKF_B_BASE + stg * MKF_B_STG;
#pragma unroll
    for (int i = 0; i < 4; i++) {
        int li = tid + i * MK_T;              // 0..2047
        int n = li >> 3, c = li & 7;          // row, 16B chunk (8 halves)
        cp16(bb + swzo(n, c), Bt + (size_t)n * 256 + k0 + c * 8);
    }
}

__global__ __launch_bounds__(MK_T, 2) void mk_layers(const float* __restrict__ hr,
                                                     const float* __restrict__ W0,
                                                     const __half* __restrict__ Bt1,
                                                     const float* __restrict__ b1,
                                                     const __half* __restrict__ Bt2,
                                                     const float* __restrict__ b2,
                                                     const __half* __restrict__ Bt3,
                                                     const float* __restrict__ b3,
                                                     const float* __restrict__ W4) {
    extern __shared__ char smem[];
    uint32_t sb = smem_u32(smem);
    int*   sIdx = (int*)(smem + MKF_IDX);
    float* sR0  = (float*)(smem + MKF_IDX + 256);
    float* sR1  = (float*)(smem + MKF_IDX + 512);

    const int tid = threadIdx.x;
    const int wid = tid >> 5, lane = tid & 31;
    const int wm = wid >> 3;            // 0..1 (32-row blocks)
    const int wn = wid & 7;             // 0..7 (32-col blocks)
    const size_t bm = (size_t)blockIdx.x * 64;
    const int er = lane >> 2;
    const int ec = (lane & 3) * 2;

    if (tid < 64) {
        size_t s = bm + tid;
        int cc = (int)(s >> 16);
        int q  = (int)(s & 65535);
        float c0 = hr[2 * q], c1 = hr[2 * q + 1];
        int idx; float r0, r1;
        corner_calc(c0, c1, cc, idx, r0, r1);
        sIdx[tid] = idx; sR0[tid] = r0; sR1[tid] = r1;
    }
    __syncthreads();

    // ---- fill h(f16) = h16(relu(hp[idx] + r0*W0[585] + r1*W0[586])) ----
    // 64 rows x 8 chunks per panel = 512 items = one pass of 512 threads
#pragma unroll
    for (int p = 0; p < HPN; p++) {
        int m = tid >> 3, c = tid & 7;
        int k = p * 64 + c * 8;
        int row = sIdx[m];
        float r0 = sR0[m], r1 = sR1[m];
        float4 h0  = __ldg((const float4*)&g_hp[(size_t)row * 256 + k]);
        float4 h1  = __ldg((const float4*)&g_hp[(size_t)row * 256 + k + 4]);
        float4 wa0 = __ldg((const float4*)&W0[585 * 256 + k]);
        float4 wa1 = __ldg((const float4*)&W0[585 * 256 + k + 4]);
        float4 wb0 = __ldg((const float4*)&W0[586 * 256 + k]);
        float4 wb1 = __ldg((const float4*)&W0[586 * 256 + k + 4]);
        __half2 x0 = __floats2half2_rn(fmaxf(h0.x + r0 * wa0.x + r1 * wb0.x, 0.f),
                                       fmaxf(h0.y + r0 * wa0.y + r1 * wb0.y, 0.f));
        __half2 x1 = __floats2half2_rn(fmaxf(h0.z + r0 * wa0.z + r1 * wb0.z, 0.f),
                                       fmaxf(h0.w + r0 * wa0.w + r1 * wb0.w, 0.f));
        __half2 x2 = __floats2half2_rn(fmaxf(h1.x + r0 * wa1.x + r1 * wb1.x, 0.f),
                                       fmaxf(h1.y + r0 * wa1.y + r1 * wb1.y, 0.f));
        __half2 x3 = __floats2half2_rn(fmaxf(h1.z + r0 * wa1.z + r1 * wb1.z, 0.f),
                                       fmaxf(h1.w + r0 * wa1.w + r1 * wb1.w, 0.f));
        uint4 o;
        o.x = *reinterpret_cast<uint32_t*>(&x0);
        o.y = *reinterpret_cast<uint32_t*>(&x1);
        o.z = *reinterpret_cast<uint32_t*>(&x2);
        o.w = *reinterpret_cast<uint32_t*>(&x3);
        *reinterpret_cast<uint4*>(smem + p * HP_AST + swzo(m, c)) = o;
    }
    __syncthreads();

    // ldmatrix geometry (fp16 k16)
    const int rw = lane & 7;
    const int jq = lane >> 3;
    const int a_r = wm * 32 + rw + (jq & 1) * 8;
    const int a_c = jq >> 1;
    const int b_r = wn * 32 + rw + (jq >> 1) * 8;
    const int b_c = jq & 1;

    const __half* Bts[3]   = {Bt1, Bt2, Bt3};
    const float* biases[3] = {b1, b2, b3};

#pragma unroll 1
    for (int L = 0; L < 3; L++) {
        const __half* Bt = Bts[L];
        const float* bias = biases[L];

        float acc[2][4][4];
#pragma unroll
        for (int i = 0; i < 2; i++)
#pragma unroll
            for (int j = 0; j < 4; j++)
#pragma unroll
                for (int v = 0; v < 4; v++) acc[i][j][v] = 0.f;

        mkf_load_B(sb, Bt, 0, 0, tid);  CP_COMMIT();
        mkf_load_B(sb, Bt, 64, 1, tid); CP_COMMIT();

#pragma unroll 1
        for (int it = 0; it < 4; it++) {
            if (it + 1 < 4) { CP_WAIT(1); } else { CP_WAIT(0); }
            __syncthreads();
            uint32_t abase = sb + it * HP_AST;          // panel it == K chunk it
            uint32_t bbase = sb + MKF_B_BASE + (it & 1) * MKF_B_STG;
#pragma unroll
            for (int ks = 0; ks < 4; ks++) {            // four k16 steps per BK=64
                int cb = ks * 2;
                uint32_t afr[2][4];
#pragma unroll
                for (int mt = 0; mt < 2; mt++)
                    ldsm4(afr[mt], abase + swzo(a_r + mt * 16, cb + a_c));
                uint32_t bfr[2][4];
#pragma unroll
                for (int gg = 0; gg < 2; gg++)
                    ldsm4(bfr[gg], bbase + swzo(b_r + gg * 16, cb + b_c));
#pragma unroll
                for (int mt = 0; mt < 2; mt++)
#pragma unroll
                    for (int nt = 0; nt < 4; nt++)
                        mma_f16(acc[mt][nt], afr[mt], &bfr[nt >> 1][(nt & 1) * 2]);
            }
            __syncthreads();
            if (it + 2 < 4) {
                mkf_load_B(sb, Bt, (it + 2) * 64, it & 1, tid);
                CP_COMMIT();
            }
        }

        if (L < 2) {
            // write acc -> h panels (f16) with bias+relu
#pragma unroll
            for (int mt = 0; mt < 2; mt++) {
#pragma unroll
                for (int nt = 0; nt < 4; nt++) {
                    int n = wn * 32 + nt * 8 + ec;
                    float bi0 = __ldg(&bias[n]);
                    float bi1 = __ldg(&bias[n + 1]);
                    int r0 = wm * 32 + mt * 16 + er;
                    int r1 = r0 + 8;
                    __half2 lo = __floats2half2_rn(fmaxf(acc[mt][nt][0] + bi0, 0.f),
                                                   fmaxf(acc[mt][nt][1] + bi1, 0.f));
                    __half2 hi = __floats2half2_rn(fmaxf(acc[mt][nt][2] + bi0, 0.f),
                                                   fmaxf(acc[mt][nt][3] + bi1, 0.f));
                    int panel = n >> 6;
                    int chunk = (n & 63) >> 3;
                    int sub = (n & 7) * 2;               // 0,4,8,12 (ec even)
                    *reinterpret_cast<__half2*>(smem + panel * HP_AST +
                                                swzo(r0, chunk) + sub) = lo;
                    *reinterpret_cast<__half2*>(smem + panel * HP_AST +
                                                swzo(r1, chunk) + sub) = hi;
                }
            }
            __syncthreads();
        } else {
            // fused final layer: h4 = relu(acc + b3); dot with W4 (__ldg); atomics
#pragma unroll
            for (int mt = 0; mt < 2; mt++) {
                float p[2][3];
#pragma unroll
                for (int h = 0; h < 2; h++)
#pragma unroll
                    for (int c = 0; c < 3; c++) p[h][c] = 0.f;
#pragma unroll
                for (int nt = 0; nt < 4; nt++) {
                    int n = wn * 32 + nt * 8 + ec;
                    float bi0 = __ldg(&bias[n]);
                    float bi1 = __ldg(&bias[n + 1]);
                    float v0 = fmaxf(acc[mt][nt][0] + bi0, 0.f);
                    float v1 = fmaxf(acc[mt][nt][1] + bi1, 0.f);
                    float v2 = fmaxf(acc[mt][nt][2] + bi0, 0.f);
                    float v3 = fmaxf(acc[mt][nt][3] + bi1, 0.f);
#pragma unroll
                    for (int c = 0; c < 3; c++) {
                        float w0 = __ldg(&W4[n * 3 + c]);
                        float w1 = __ldg(&W4[(n + 1) * 3 + c]);
                        p[0][c] += v0 * w0 + v1 * w1;
                        p[1][c] += v2 * w0 + v3 * w1;
                    }
                }
#pragma unroll
                for (int h = 0; h < 2; h++)
#pragma unroll
                    for (int c = 0; c < 3; c++) {
                        p[h][c] += __shfl_xor_sync(0xFFFFFFFFu, p[h][c], 1);
                        p[h][c] += __shfl_xor_sync(0xFFFFFFFFu, p[h][c], 2);
                    }
                if ((lane & 3) == 0) {
                    size_t m0 = bm + wm * 32 + mt * 16 + er;
#pragma unroll
                    for (int c = 0; c < 3; c++) {
                        atomicAdd(&g_pred[m0 * 3 + c],       p[0][c]);
                        atomicAdd(&g_pred[(m0 + 8) * 3 + c], p[1][c]);
                    }
                }
            }
        }
    }
}

// ---------------------------------------------------------------------------
// im2col (padded, tf32-rounded)
// ---------------------------------------------------------------------------
__global__ void build_X(const float* __restrict__ mf, const float* __restrict__ mask) {
    int p = blockIdx.x;
    int t = threadIdx.x;
    if (t >= K0P) return;
    int y = p >> 7, x = p & 127;
    float v = 0.f;
    if (t < K1) {
        int c = t / 9, r = t - c * 9;
        int ki = r / 3, kj = r - ki * 3;
        int yy = y + ki - 1, xx = x + kj - 1;
        if (yy >= 0 && yy < FH && xx >= 0 && xx < FW) {
            v = (c < 64) ? mf[(c << 14) + (yy << 7) + xx] : mask[(yy << 7) + xx];
        }
        v = rnd_tf32(v);
    }
    g_X[p * K0P + t] = v;
}

// ---------------------------------------------------------------------------
// Merged prep: Wt0 (tf32) + Wt1..3 (fp16 transposed) + zero g_pred
// ---------------------------------------------------------------------------
#define SEG0 (256 * K0P)
#define SEG1 (256 * 256)
#define PREP_TOT (SEG0 + 3 * SEG1 + SN * 3)
__global__ void prep_all(const float* __restrict__ W0, const float* __restrict__ W1,
                         const float* __restrict__ W2, const float* __restrict__ W3) {
    int i = blockIdx.x * blockDim.x + threadIdx.x;
    if (i >= PREP_TOT) return;
    if (i < SEG0) {
        int n = i / K0P, k = i - n * K0P;
        g_Wt0[i] = (k < K1) ? rnd_tf32(W0[k * 256 + n]) : 0.f;
        return;
    }
    i -= SEG0;
    if (i < SEG1) { int n = i >> 8, k = i & 255; g_Wth1[i] = __float2half_rn(W1[k * 256 + n]); return; }
    i -= SEG1;
    if (i < SEG1) { int n = i >> 8, k = i & 255; g_Wth2[i] = __float2half_rn(W2[k * 256 + n]); return; }
    i -= SEG1;
    if (i < SEG1) { int n = i >> 8, k = i & 255; g_Wth3[i] = __float2half_rn(W3[k * 256 + n]); return; }
    i -= SEG1;
    g_pred[i] = 0.f;
}

// ---------------------------------------------------------------------------
// local ensemble (adds b4)
// ---------------------------------------------------------------------------
__global__ void ensemble(const float* __restrict__ hr, const float* __restrict__ b4,
                         float* __restrict__ out) {
    int q = blockIdx.x * blockDim.x + threadIdx.x;
    if (q >= QN) return;
    float c0 = hr[2 * q], c1 = hr[2 * q + 1];
    float b40 = __ldg(&b4[0]), b41 = __ldg(&b4[1]), b42 = __ldg(&b4[2]);
    float area[4];
#pragma unroll
    for (int cc = 0; cc < 4; cc++) {
        int idx; float r0, r1;
        corner_calc(c0, c1, cc, idx, r0, r1);
        area[cc] = fabsf(r0 * r1) + 1e-9f;
    }
    float tot = area[0] + area[1] + area[2] + area[3];
    float o0 = 0.f, o1 = 0.f, o2 = 0.f;
#pragma unroll
    for (int cc = 0; cc < 4; cc++) {
        float w = area[3 - cc] / tot;
        size_t s = (size_t)cc * QN + q;
        o0 += (g_pred[s * 3 + 0] + b40) * w;
        o1 += (g_pred[s * 3 + 1] + b41) * w;
        o2 += (g_pred[s * 3 + 2] + b42) * w;
    }
    out[0 * QN + q] = o0;
    out[1 * QN + q] = o1;
    out[2 * QN + q] = o2;
}

// ---------------------------------------------------------------------------
// Launch
// ---------------------------------------------------------------------------
extern "C" void kernel_launch(void* const* d_in, const int* in_sizes, int n_in,
                              void* d_out, int out_size) {
    const float* mf   = (const float*)d_in[0];
    const float* mask = (const float*)d_in[1];
    const float* hr = (const float*)d_in[3];
    const float* W0 = (const float*)d_in[4];
    const float* b0 = (const float*)d_in[5];
    const float* W1 = (const float*)d_in[6];
    const float* b1 = (const float*)d_in[7];
    const float* W2 = (const float*)d_in[8];
    const float* b2 = (const float*)d_in[9];
    const float* W3 = (const float*)d_in[10];
    const float* b3 = (const float*)d_in[11];
    const float* W4 = (const float*)d_in[12];
    const float* b4 = (const float*)d_in[13];
    float* out = (float*)d_out;

    void *pX, *pWt0, *pW1, *pW2, *pW3, *pHp;
    cudaGetSymbolAddress(&pX,   g_X);
    cudaGetSymbolAddress(&pWt0, g_Wt0);
    cudaGetSymbolAddress(&pW1,  g_Wth1);
    cudaGetSymbolAddress(&pW2,  g_Wth2);
    cudaGetSymbolAddress(&pW3,  g_Wth3);
    cudaGetSymbolAddress(&pHp,  g_hp);

    cudaFuncSetAttribute(gemm_l0,   cudaFuncAttributeMaxDynamicSharedMemorySize, SMEM_GEMM);
    cudaFuncSetAttribute(mk_layers, cudaFuncAttributeMaxDynamicSharedMemorySize, SMEM_MKF);

    build_X<<<NPIX, 640>>>(mf, mask);
    prep_all<<<(PREP_TOT + 255) / 256, 256>>>(W0, W1, W2, W3);

    // hp = X @ W0 + b0 (tf32, proven)
    gemm_l0<<<dim3(2, NPIX / 128), 256, SMEM_GEMM>>>((const float*)pX, (const float*)pWt0,
                                                     b0, (float*)pHp, K0P);

    // layers 1-3 fused, fp16 (BM=64, 512 threads, 2 CTAs/SM)
    mk_layers<<<SN / 64, MK_T, SMEM_MKF>>>(hr, W0,
                                           (const __half*)pW1, b1,
                                           (const __half*)pW2, b2,
                                           (const __half*)pW3, b3, W4);

    ensemble<<<QN / 256, 256>>>(hr, b4, out);
}

// round 14
// speedup vs baseline: 1.8957x; 1.1300x over previous
#include <cuda_runtime.h>
#include <cuda_fp16.h>
#include <cstdint>

// ---------------------------------------------------------------------------
// Problem constants
// ---------------------------------------------------------------------------
#define FH 128
#define FW 128
#define NPIX (FH*FW)       // 16384
#define QN 65536           // queries
#define SN (4*QN)          // 262144 corner samples
#define K1 585             // valid unfold dims
#define K0P 608            // padded K for layer0 (mult of 32)
#define NH 256

// ---------------------------------------------------------------------------
// Scratch
// ---------------------------------------------------------------------------
__device__ __align__(128) float  g_X[NPIX * K0P];
__device__ __align__(128) float  g_Wt0[NH * K0P];      // tf32 layer-0 weights
__device__ __align__(128) __half g_Wth1[NH * NH];      // fp16 transposed weights
__device__ __align__(128) __half g_Wth2[NH * NH];
__device__ __align__(128) __half g_Wth3[NH * NH];
__device__ __align__(128) float  g_hp[NPIX * NH];
__device__ __align__(128) float  g_pred[SN * 3];

// ---------------------------------------------------------------------------
// PTX helpers (compute_103-portable) — proven
// ---------------------------------------------------------------------------
__device__ __forceinline__ uint32_t smem_u32(const void* p) {
    uint32_t a;
    asm("{ .reg .u64 t; cvta.to.shared.u64 t, %1; cvt.u32.u64 %0, t; }" : "=r"(a) : "l"(p));
    return a;
}
__device__ __forceinline__ float rnd_tf32(float x) {
    uint32_t r;
    asm("cvt.rna.tf32.f32 %0, %1;" : "=r"(r) : "f"(x));
    return __uint_as_float(r);
}
__device__ __forceinline__ void cp16(uint32_t dst, const void* src) {
    asm volatile("cp.async.cg.shared.global [%0], [%1], 16;" :: "r"(dst), "l"(src));
}
#define CP_COMMIT() asm volatile("cp.async.commit_group;" ::: "memory")
#define CP_WAIT(n)  asm volatile("cp.async.wait_group %0;" :: "n"(n) : "memory")

__device__ __forceinline__ void ldsm4(uint32_t* r, uint32_t addr) {
    asm volatile("ldmatrix.sync.aligned.m8n8.x4.shared.b16 {%0,%1,%2,%3}, [%4];"
                 : "=r"(r[0]), "=r"(r[1]), "=r"(r[2]), "=r"(r[3]) : "r"(addr));
}
__device__ __forceinline__ void mma_tf32(float* d, const uint32_t* a, const uint32_t* b) {
    asm volatile(
        "mma.sync.aligned.m16n8k8.row.col.f32.tf32.tf32.f32 "
        "{%0,%1,%2,%3}, {%4,%5,%6,%7}, {%8,%9}, {%0,%1,%2,%3};"
        : "+f"(d[0]), "+f"(d[1]), "+f"(d[2]), "+f"(d[3])
        : "r"(a[0]), "r"(a[1]), "r"(a[2]), "r"(a[3]), "r"(b[0]), "r"(b[1]));
}
__device__ __forceinline__ void mma_f16(float* d, const uint32_t* a, const uint32_t* b) {
    asm volatile(
        "mma.sync.aligned.m16n8k16.row.col.f32.f16.f16.f32 "
        "{%0,%1,%2,%3}, {%4,%5,%6,%7}, {%8,%9}, {%0,%1,%2,%3};"
        : "+f"(d[0]), "+f"(d[1]), "+f"(d[2]), "+f"(d[3])
        : "r"(a[0]), "r"(a[1]), "r"(a[2]), "r"(a[3]), "r"(b[0]), "r"(b[1]));
}

// stage format: rows x 128B, chunk-XOR swizzle (proven)
__device__ __forceinline__ uint32_t swzo(int r, int c) {
    return (uint32_t)(r * 128 + ((c ^ (r & 7)) << 4));
}

// ---------------------------------------------------------------------------
// Standalone tf32 GEMM for layer 0 (R8/R10-proven): 3-stage, BM=128, BN=128
// ---------------------------------------------------------------------------
#define AST 16384
#define NST 3
#define B_BASE3 (NST * AST)
#define SMEM_GEMM (2 * NST * AST)

__device__ __forceinline__ void load_A3(uint32_t sb, const float* __restrict__ A,
                                        size_t bm, int k0, int stg, int K, int tid) {
    uint32_t ab = sb + stg * AST;
#pragma unroll
    for (int i = 0; i < 4; i++) {
        int li = tid + i * 256;
        int m = li >> 3, c = li & 7;
        cp16(ab + swzo(m, c), A + (bm + m) * (size_t)K + k0 + c * 4);
    }
}
__device__ __forceinline__ void load_B3(uint32_t sb, const float* __restrict__ Bt,
                                        int bn, int k0, int stg, int K, int tid) {
    uint32_t bb = sb + B_BASE3 + stg * AST;
#pragma unroll
    for (int i = 0; i < 4; i++) {
        int li = tid + i * 256;
        int n = li >> 3, c = li & 7;
        cp16(bb + swzo(n, c), Bt + (size_t)(bn + n) * K + k0 + c * 4);
    }
}

__global__ __launch_bounds__(256, 2) void gemm_l0(const float* __restrict__ A,
                                                  const float* __restrict__ Bt,
                                                  const float* __restrict__ bias,
                                                  float* __restrict__ C, int K) {
    extern __shared__ char smem[];
    uint32_t sb = smem_u32(smem);
    const int tid = threadIdx.x;
    const int wid = tid >> 5, lane = tid & 31;
    const int wm = wid >> 2, wn = wid & 3;
    const size_t bm = (size_t)blockIdx.y * 128;
    const int bn = blockIdx.x * 128;
    const int nit = K >> 5;

    float acc[4][4][4];
#pragma unroll
    for (int i = 0; i < 4; i++)
#pragma unroll
        for (int j = 0; j < 4; j++)
#pragma unroll
            for (int v = 0; v < 4; v++) acc[i][j][v] = 0.f;

    load_A3(sb, A, bm, 0, 0, K, tid);  load_B3(sb, Bt, bn, 0, 0, K, tid);  CP_COMMIT();
    load_A3(sb, A, bm, 32, 1, K, tid); load_B3(sb, Bt, bn, 32, 1, K, tid); CP_COMMIT();

    const int rw = lane & 7;
    const int j  = lane >> 3;
    const int a_r = wm * 64 + rw + (j & 1) * 8;
    const int a_c = j >> 1;
    const int b_r = wn * 32 + rw + (j >> 1) * 8;
    const int b_c = j & 1;

    for (int it = 0; it < nit; it++) {
        if (it + 1 < nit) { CP_WAIT(1); } else { CP_WAIT(0); }
        __syncthreads();
        if (it + 2 < nit) {
            int stg = (it + 2) % NST;
            load_A3(sb, A, bm, (it + 2) * 32, stg, K, tid);
            load_B3(sb, Bt, bn, (it + 2) * 32, stg, K, tid);
            CP_COMMIT();
        }
        int stg = it % NST;
        uint32_t abase = sb + stg * AST;
        uint32_t bbase = sb + B_BASE3 + stg * AST;
#pragma unroll
        for (int ks = 0; ks < 4; ks++) {
            uint32_t afr[4][4];
#pragma unroll
            for (int mt = 0; mt < 4; mt++)
                ldsm4(afr[mt], abase + swzo(a_r + mt * 16, ks * 2 + a_c));
            uint32_t bfr[2][4];
#pragma unroll
            for (int gg = 0; gg < 2; gg++)
                ldsm4(bfr[gg], bbase + swzo(b_r + gg * 16, ks * 2 + b_c));
#pragma unroll
            for (int mt = 0; mt < 4; mt++)
#pragma unroll
                for (int nt = 0; nt < 4; nt++)
                    mma_tf32(acc[mt][nt], afr[mt], &bfr[nt >> 1][(nt & 1) * 2]);
        }
    }

    const int er = lane >> 2;
    const int ec = (lane & 3) * 2;
#pragma unroll
    for (int mt = 0; mt < 4; mt++) {
#pragma unroll
        for (int nt = 0; nt < 4; nt++) {
            int n = bn + wn * 32 + nt * 8 + ec;
            float bi0 = __ldg(&bias[n]);
            float bi1 = __ldg(&bias[n + 1]);
            size_t m0 = bm + wm * 64 + mt * 16 + er;
            *reinterpret_cast<float2*>(&C[m0 * 256 + n]) =
                make_float2(acc[mt][nt][0] + bi0, acc[mt][nt][1] + bi1);
            *reinterpret_cast<float2*>(&C[(m0 + 8) * 256 + n]) =
                make_float2(acc[mt][nt][2] + bi0, acc[mt][nt][3] + bi1);
        }
    }
}

// ---------------------------------------------------------------------------
// Corner geometry (proven)
// ---------------------------------------------------------------------------
__device__ __forceinline__ void corner_calc(float c0, float c1, int cc,
                                            int& idx, float& rel0, float& rel1) {
    const float rr = 1.0f / 128.0f;
    float vx = (cc & 2) ? 1.f : -1.f;
    float vy = (cc & 1) ? 1.f : -1.f;
    float cy = fminf(fmaxf(c0 + vx * rr + 1e-6f, -1.f + 1e-6f), 1.f - 1e-6f);
    float cx = fminf(fmaxf(c1 + vy * rr + 1e-6f, -1.f + 1e-6f), 1.f - 1e-6f);
    int iy = (int)rintf(((cy + 1.0f) * 128.0f - 1.0f) * 0.5f);
    int ix = (int)rintf(((cx + 1.0f) * 128.0f - 1.0f) * 0.5f);
    iy = min(max(iy, 0), 127);
    ix = min(max(ix, 0), 127);
    float qy = -1.0f + (2.0f * (float)iy + 1.0f) / 128.0f;
    float qx = -1.0f + (2.0f * (float)ix + 1.0f) / 128.0f;
    rel0 = (c0 - qy) * 128.0f;
    rel1 = (c1 - qx) * 128.0f;
    idx = iy * 128 + ix;
}

// ---------------------------------------------------------------------------
// fp16 megakernel: layers 1-3 fused. BM=64 samples/CTA, BN=256, 256 threads,
// 2 CTAs/SM. h (64x256 f16) in 4 swizzled 8KB panels.
// B: fp16, BK=64, 2-stage x 32KB, proven dual-sync loop (nit=4).
// Warps 2(m) x 4(n), warp tile 32x64 (m16n8k16) — R12-proven 0.375 LDSM/MMA.
// ---------------------------------------------------------------------------
#define HP_AST 8192                           // one h panel (64 rows x 128B)
#define HPN 4
#define MKF_B_BASE (HPN * HP_AST)             // 32768
#define MKF_B_STG  32768                      // 256 rows x 128B
#define MKF_IDX    (MKF_B_BASE + 2 * MKF_B_STG)  // 98304
#define SMEM_MKF   (MKF_IDX + 768)            // 99072  (x2 CTAs = 198KB/SM)
#define MK_T 256

__device__ __forceinline__ void mkf_load_B(uint32_t sb, const __half* __restrict__ Bt,
                                           int k0, int stg, int tid) {
    uint32_t bb = sb + MKF_B_BASE + stg * MKF_B_STG;
#pragma unroll
    for (int i = 0; i < 8; i++) {
        int li = tid + i * MK_T;              // 0..2047
        int n = li >> 3, c = li & 7;          // row, 16B chunk (8 halves)
        cp16(bb + swzo(n, c), Bt + (size_t)n * 256 + k0 + c * 8);
    }
}

__global__ __launch_bounds__(MK_T, 2) void mk_layers(const float* __restrict__ hr,
                                                     const float* __restrict__ W0,
                                                     const __half* __restrict__ Bt1,
                                                     const float* __restrict__ b1,
                                                     const __half* __restrict__ Bt2,
                                                     const float* __restrict__ b2,
                                                     const __half* __restrict__ Bt3,
                                                     const float* __restrict__ b3,
                                                     const float* __restrict__ W4) {
    extern __shared__ char smem[];
    uint32_t sb = smem_u32(smem);
    int*   sIdx = (int*)(smem + MKF_IDX);
    float* sR0  = (float*)(smem + MKF_IDX + 256);
    float* sR1  = (float*)(smem + MKF_IDX + 512);

    const int tid = threadIdx.x;
    const int wid = tid >> 5, lane = tid & 31;
    const int wm = wid >> 2;            // 0..1 (32-row blocks)
    const int wn = wid & 3;             // 0..3 (64-col blocks)
    const size_t bm = (size_t)blockIdx.x * 64;
    const int er = lane >> 2;
    const int ec = (lane & 3) * 2;

    if (tid < 64) {
        size_t s = bm + tid;
        int cc = (int)(s >> 16);
        int q  = (int)(s & 65535);
        float c0 = hr[2 * q], c1 = hr[2 * q + 1];
        int idx; float r0, r1;
        corner_calc(c0, c1, cc, idx, r0, r1);
        sIdx[tid] = idx; sR0[tid] = r0; sR1[tid] = r1;
    }
    __syncthreads();

    // ---- fill h(f16) = h16(relu(hp[idx] + r0*W0[585] + r1*W0[586])) ----
    // 64 rows x 8 chunks per panel = 512 items; 256 threads -> 2 passes
#pragma unroll
    for (int p = 0; p < HPN; p++) {
#pragma unroll
        for (int i = 0; i < 2; i++) {
            int li = tid + i * MK_T;          // 0..511
            int m = li >> 3, c = li & 7;
            int k = p * 64 + c * 8;
            int row = sIdx[m];
            float r0 = sR0[m], r1 = sR1[m];
            float4 h0  = __ldg((const float4*)&g_hp[(size_t)row * 256 + k]);
            float4 h1  = __ldg((const float4*)&g_hp[(size_t)row * 256 + k + 4]);
            float4 wa0 = __ldg((const float4*)&W0[585 * 256 + k]);
            float4 wa1 = __ldg((const float4*)&W0[585 * 256 + k + 4]);
            float4 wb0 = __ldg((const float4*)&W0[586 * 256 + k]);
            float4 wb1 = __ldg((const float4*)&W0[586 * 256 + k + 4]);
            __half2 x0 = __floats2half2_rn(fmaxf(h0.x + r0 * wa0.x + r1 * wb0.x, 0.f),
                                           fmaxf(h0.y + r0 * wa0.y + r1 * wb0.y, 0.f));
            __half2 x1 = __floats2half2_rn(fmaxf(h0.z + r0 * wa0.z + r1 * wb0.z, 0.f),
                                           fmaxf(h0.w + r0 * wa0.w + r1 * wb0.w, 0.f));
            __half2 x2 = __floats2half2_rn(fmaxf(h1.x + r0 * wa1.x + r1 * wb1.x, 0.f),
                                           fmaxf(h1.y + r0 * wa1.y + r1 * wb1.y, 0.f));
            __half2 x3 = __floats2half2_rn(fmaxf(h1.z + r0 * wa1.z + r1 * wb1.z, 0.f),
                                           fmaxf(h1.w + r0 * wa1.w + r1 * wb1.w, 0.f));
            uint4 o;
            o.x = *reinterpret_cast<uint32_t*>(&x0);
            o.y = *reinterpret_cast<uint32_t*>(&x1);
            o.z = *reinterpret_cast<uint32_t*>(&x2);
            o.w = *reinterpret_cast<uint32_t*>(&x3);
            *reinterpret_cast<uint4*>(smem + p * HP_AST + swzo(m, c)) = o;
        }
    }
    __syncthreads();

    // ldmatrix geometry (fp16 k16)
    const int rw = lane & 7;
    const int jq = lane >> 3;
    const int a_r = wm * 32 + rw + (jq & 1) * 8;
    const int a_c = jq >> 1;
    const int b_r = wn * 64 + rw + (jq >> 1) * 8;
    const int b_c = jq & 1;

    const __half* Bts[3]   = {Bt1, Bt2, Bt3};
    const float* biases[3] = {b1, b2, b3};

#pragma unroll 1
    for (int L = 0; L < 3; L++) {
        const __half* Bt = Bts[L];
        const float* bias = biases[L];

        float acc[2][8][4];
#pragma unroll
        for (int i = 0; i < 2; i++)
#pragma unroll
            for (int j = 0; j < 8; j++)
#pragma unroll
                for (int v = 0; v < 4; v++) acc[i][j][v] = 0.f;

        mkf_load_B(sb, Bt, 0, 0, tid);  CP_COMMIT();
        mkf_load_B(sb, Bt, 64, 1, tid); CP_COMMIT();

#pragma unroll 1
        for (int it = 0; it < 4; it++) {
            if (it + 1 < 4) { CP_WAIT(1); } else { CP_WAIT(0); }
            __syncthreads();
            uint32_t abase = sb + it * HP_AST;          // panel it == K chunk it
            uint32_t bbase = sb + MKF_B_BASE + (it & 1) * MKF_B_STG;
#pragma unroll
            for (int ks = 0; ks < 4; ks++) {            // four k16 steps per BK=64
                int cb = ks * 2;
                uint32_t afr[2][4];
#pragma unroll
                for (int mt = 0; mt < 2; mt++)
                    ldsm4(afr[mt], abase + swzo(a_r + mt * 16, cb + a_c));
                uint32_t bfr[4][4];
#pragma unroll
                for (int gg = 0; gg < 4; gg++)
                    ldsm4(bfr[gg], bbase + swzo(b_r + gg * 16, cb + b_c));
#pragma unroll
                for (int mt = 0; mt < 2; mt++)
#pragma unroll
                    for (int nt = 0; nt < 8; nt++)
                        mma_f16(acc[mt][nt], afr[mt], &bfr[nt >> 1][(nt & 1) * 2]);
            }
            __syncthreads();
            if (it + 2 < 4) {
                mkf_load_B(sb, Bt, (it + 2) * 64, it & 1, tid);
                CP_COMMIT();
            }
        }

        if (L < 2) {
            // write acc -> h panels (f16) with bias+relu
#pragma unroll
            for (int mt = 0; mt < 2; mt++) {
#pragma unroll
                for (int nt = 0; nt < 8; nt++) {
                    int n = wn * 64 + nt * 8 + ec;
                    float bi0 = __ldg(&bias[n]);
                    float bi1 = __ldg(&bias[n + 1]);
                    int r0 = wm * 32 + mt * 16 + er;
                    int r1 = r0 + 8;
                    __half2 lo = __floats2half2_rn(fmaxf(acc[mt][nt][0] + bi0, 0.f),
                                                   fmaxf(acc[mt][nt][1] + bi1, 0.f));
                    __half2 hi = __floats2half2_rn(fmaxf(acc[mt][nt][2] + bi0, 0.f),
                                                   fmaxf(acc[mt][nt][3] + bi1, 0.f));
                    int panel = n >> 6;
                    int chunk = (n & 63) >> 3;
                    int sub = (n & 7) * 2;               // 0,4,8,12 (ec even)
                    *reinterpret_cast<__half2*>(smem + panel * HP_AST +
                                                swzo(r0, chunk) + sub) = lo;
                    *reinterpret_cast<__half2*>(smem + panel * HP_AST +
                                                swzo(r1, chunk) + sub) = hi;
                }
            }
            __syncthreads();
        } else {
            // fused final layer: h4 = relu(acc + b3); dot with W4 (__ldg); atomics
#pragma unroll
            for (int mt = 0; mt < 2; mt++) {
                float p[2][3];
#pragma unroll
                for (int h = 0; h < 2; h++)
#pragma unroll
                    for (int c = 0; c < 3; c++) p[h][c] = 0.f;
#pragma unroll
                for (int nt = 0; nt < 8; nt++) {
                    int n = wn * 64 + nt * 8 + ec;
                    float bi0 = __ldg(&bias[n]);
                    float bi1 = __ldg(&bias[n + 1]);
                    float v0 = fmaxf(acc[mt][nt][0] + bi0, 0.f);
                    float v1 = fmaxf(acc[mt][nt][1] + bi1, 0.f);
                    float v2 = fmaxf(acc[mt][nt][2] + bi0, 0.f);
                    float v3 = fmaxf(acc[mt][nt][3] + bi1, 0.f);
#pragma unroll
                    for (int c = 0; c < 3; c++) {
                        float w0 = __ldg(&W4[n * 3 + c]);
                        float w1 = __ldg(&W4[(n + 1) * 3 + c]);
                        p[0][c] += v0 * w0 + v1 * w1;
                        p[1][c] += v2 * w0 + v3 * w1;
                    }
                }
#pragma unroll
                for (int h = 0; h < 2; h++)
#pragma unroll
                    for (int c = 0; c < 3; c++) {
                        p[h][c] += __shfl_xor_sync(0xFFFFFFFFu, p[h][c], 1);
                        p[h][c] += __shfl_xor_sync(0xFFFFFFFFu, p[h][c], 2);
                    }
                if ((lane & 3) == 0) {
                    size_t m0 = bm + wm * 32 + mt * 16 + er;
#pragma unroll
                    for (int c = 0; c < 3; c++) {
                        atomicAdd(&g_pred[m0 * 3 + c],       p[0][c]);
                        atomicAdd(&g_pred[(m0 + 8) * 3 + c], p[1][c]);
                    }
                }
            }
        }
    }
}

// ---------------------------------------------------------------------------
// im2col (padded, tf32-rounded)
// ---------------------------------------------------------------------------
__global__ void build_X(const float* __restrict__ mf, const float* __restrict__ mask) {
    int p = blockIdx.x;
    int t = threadIdx.x;
    if (t >= K0P) return;
    int y = p >> 7, x = p & 127;
    float v = 0.f;
    if (t < K1) {
        int c = t / 9, r = t - c * 9;
        int ki = r / 3, kj = r - ki * 3;
        int yy = y + ki - 1, xx = x + kj - 1;
        if (yy >= 0 && yy < FH && xx >= 0 && xx < FW) {
            v = (c < 64) ? mf[(c << 14) + (yy << 7) + xx] : mask[(yy << 7) + xx];
        }
        v = rnd_tf32(v);
    }
    g_X[p * K0P + t] = v;
}

// ---------------------------------------------------------------------------
// Merged prep: Wt0 (tf32) + Wt1..3 (fp16 transposed) + zero g_pred
// ---------------------------------------------------------------------------
#define SEG0 (256 * K0P)
#define SEG1 (256 * 256)
#define PREP_TOT (SEG0 + 3 * SEG1 + SN * 3)
__global__ void prep_all(const float* __restrict__ W0, const float* __restrict__ W1,
                         const float* __restrict__ W2, const float* __restrict__ W3) {
    int i = blockIdx.x * blockDim.x + threadIdx.x;
    if (i >= PREP_TOT) return;
    if (i < SEG0) {
        int n = i / K0P, k = i - n * K0P;
        g_Wt0[i] = (k < K1) ? rnd_tf32(W0[k * 256 + n]) : 0.f;
        return;
    }
    i -= SEG0;
    if (i < SEG1) { int n = i >> 8, k = i & 255; g_Wth1[i] = __float2half_rn(W1[k * 256 + n]); return; }
    i -= SEG1;
    if (i < SEG1) { int n = i >> 8, k = i & 255; g_Wth2[i] = __float2half_rn(W2[k * 256 + n]); return; }
    i -= SEG1;
    if (i < SEG1) { int n = i >> 8, k = i & 255; g_Wth3[i] = __float2half_rn(W3[k * 256 + n]); return; }
    i -= SEG1;
    g_pred[i] = 0.f;
}

// ---------------------------------------------------------------------------
// local ensemble (adds b4)
// ---------------------------------------------------------------------------
__global__ void ensemble(const float* __restrict__ hr, const float* __restrict__ b4,
                         float* __restrict__ out) {
    int q = blockIdx.x * blockDim.x + threadIdx.x;
    if (q >= QN) return;
    float c0 = hr[2 * q], c1 = hr[2 * q + 1];
    float b40 = __ldg(&b4[0]), b41 = __ldg(&b4[1]), b42 = __ldg(&b4[2]);
    float area[4];
#pragma unroll
    for (int cc = 0; cc < 4; cc++) {
        int idx; float r0, r1;
        corner_calc(c0, c1, cc, idx, r0, r1);
        area[cc] = fabsf(r0 * r1) + 1e-9f;
    }
    float tot = area[0] + area[1] + area[2] + area[3];
    float o0 = 0.f, o1 = 0.f, o2 = 0.f;
#pragma unroll
    for (int cc = 0; cc < 4; cc++) {
        float w = area[3 - cc] / tot;
        size_t s = (size_t)cc * QN + q;
        o0 += (g_pred[s * 3 + 0] + b40) * w;
        o1 += (g_pred[s * 3 + 1] + b41) * w;
        o2 += (g_pred[s * 3 + 2] + b42) * w;
    }
    out[0 * QN + q] = o0;
    out[1 * QN + q] = o1;
    out[2 * QN + q] = o2;
}

// ---------------------------------------------------------------------------
// Launch
// ---------------------------------------------------------------------------
extern "C" void kernel_launch(void* const* d_in, const int* in_sizes, int n_in,
                              void* d_out, int out_size) {
    const float* mf   = (const float*)d_in[0];
    const float* mask = (const float*)d_in[1];
    const float* hr = (const float*)d_in[3];
    const float* W0 = (const float*)d_in[4];
    const float* b0 = (const float*)d_in[5];
    const float* W1 = (const float*)d_in[6];
    const float* b1 = (const float*)d_in[7];
    const float* W2 = (const float*)d_in[8];
    const float* b2 = (const float*)d_in[9];
    const float* W3 = (const float*)d_in[10];
    const float* b3 = (const float*)d_in[11];
    const float* W4 = (const float*)d_in[12];
    const float* b4 = (const float*)d_in[13];
    float* out = (float*)d_out;

    void *pX, *pWt0, *pW1, *pW2, *pW3, *pHp;
    cudaGetSymbolAddress(&pX,   g_X);
    cudaGetSymbolAddress(&pWt0, g_Wt0);
    cudaGetSymbolAddress(&pW1,  g_Wth1);
    cudaGetSymbolAddress(&pW2,  g_Wth2);
    cudaGetSymbolAddress(&pW3,  g_Wth3);
    cudaGetSymbolAddress(&pHp,  g_hp);

    cudaFuncSetAttribute(gemm_l0,   cudaFuncAttributeMaxDynamicSharedMemorySize, SMEM_GEMM);
    cudaFuncSetAttribute(mk_layers, cudaFuncAttributeMaxDynamicSharedMemorySize, SMEM_MKF);

    build_X<<<NPIX, 640>>>(mf, mask);
    prep_all<<<(PREP_TOT + 255) / 256, 256>>>(W0, W1, W2, W3);

    // hp = X @ W0 + b0 (tf32, proven)
    gemm_l0<<<dim3(2, NPIX / 128), 256, SMEM_GEMM>>>((const float*)pX, (const float*)pWt0,
                                                     b0, (float*)pHp, K0P);

    // layers 1-3 fused, fp16 (BM=64, 256 threads, warp tile 32x64, 2 CTAs/SM)
    mk_layers<<<SN / 64, MK_T, SMEM_MKF>>>(hr, W0,
                                           (const __half*)pW1, b1,
                                           (const __half*)pW2, b2,
                                           (const __half*)pW3, b3, W4);

    ensemble<<<QN / 256, 256>>>(hr, b4, out);
}

// round 15
// speedup vs baseline: 1.9924x; 1.0510x over previous
#include <cuda_runtime.h>
#include <cuda_fp16.h>
#include <cstdint>

// ---------------------------------------------------------------------------
// Problem constants
// ---------------------------------------------------------------------------
#define FH 128
#define FW 128
#define NPIX (FH*FW)       // 16384
#define QN 65536           // queries
#define SN (4*QN)          // 262144 corner samples
#define K1 585             // valid unfold dims
#define K0P 640            // padded K for layer0 (mult of 64)
#define NH 256

// ---------------------------------------------------------------------------
// Scratch
// ---------------------------------------------------------------------------
__device__ __align__(128) __half g_Xh[NPIX * K0P];
__device__ __align__(128) __half g_Wth0[NH * K0P];     // fp16 transposed W0 (conv rows)
__device__ __align__(128) __half g_Wth1[NH * NH];
__device__ __align__(128) __half g_Wth2[NH * NH];
__device__ __align__(128) __half g_Wth3[NH * NH];
__device__ __align__(128) float  g_hp[NPIX * NH];
__device__ __align__(128) float  g_pred[SN * 3];

// ---------------------------------------------------------------------------
// PTX helpers (compute_103-portable) — proven
// ---------------------------------------------------------------------------
__device__ __forceinline__ uint32_t smem_u32(const void* p) {
    uint32_t a;
    asm("{ .reg .u64 t; cvta.to.shared.u64 t, %1; cvt.u32.u64 %0, t; }" : "=r"(a) : "l"(p));
    return a;
}
__device__ __forceinline__ void cp16(uint32_t dst, const void* src) {
    asm volatile("cp.async.cg.shared.global [%0], [%1], 16;" :: "r"(dst), "l"(src));
}
#define CP_COMMIT() asm volatile("cp.async.commit_group;" ::: "memory")
#define CP_WAIT(n)  asm volatile("cp.async.wait_group %0;" :: "n"(n) : "memory")

__device__ __forceinline__ void ldsm4(uint32_t* r, uint32_t addr) {
    asm volatile("ldmatrix.sync.aligned.m8n8.x4.shared.b16 {%0,%1,%2,%3}, [%4];"
                 : "=r"(r[0]), "=r"(r[1]), "=r"(r[2]), "=r"(r[3]) : "r"(addr));
}
__device__ __forceinline__ void mma_f16(float* d, const uint32_t* a, const uint32_t* b) {
    asm volatile(
        "mma.sync.aligned.m16n8k16.row.col.f32.f16.f16.f32 "
        "{%0,%1,%2,%3}, {%4,%5,%6,%7}, {%8,%9}, {%0,%1,%2,%3};"
        : "+f"(d[0]), "+f"(d[1]), "+f"(d[2]), "+f"(d[3])
        : "r"(a[0]), "r"(a[1]), "r"(a[2]), "r"(a[3]), "r"(b[0]), "r"(b[1]));
}

// stage format: rows x 128B, chunk-XOR swizzle (proven)
__device__ __forceinline__ uint32_t swzo(int r, int c) {
    return (uint32_t)(r * 128 + ((c ^ (r & 7)) << 4));
}

// ---------------------------------------------------------------------------
// Layer-0 fp16 GEMM: hp[M,256] = X[M,640] @ Wth0^T + b0 (fp32 out)
// BM=128, BN=128, BK=64, 256 threads, warps 2(m)x4(n), tile 64x32 (R12-proven)
// ---------------------------------------------------------------------------
#define L0_AST 16384
#define SMEM_L0 (4 * L0_AST)     // A x2 + B x2

__device__ __forceinline__ void l0_load(uint32_t base, const __half* __restrict__ src,
                                        size_t row0, int k0, int tid) {
#pragma unroll
    for (int i = 0; i < 4; i++) {
        int li = tid + i * 256;
        int m = li >> 3, c = li & 7;
        cp16(base + swzo(m, c), src + (row0 + m) * (size_t)K0P + k0 + c * 8);
    }
}

__global__ __launch_bounds__(256, 2) void gemm_l0(const __half* __restrict__ X,
                                                  const __half* __restrict__ Bt,
                                                  const float* __restrict__ bias,
                                                  float* __restrict__ C) {
    extern __shared__ char smem[];
    uint32_t sb = smem_u32(smem);
    const int tid = threadIdx.x;
    const int wid = tid >> 5, lane = tid & 31;
    const int wm = wid >> 2, wn = wid & 3;
    const size_t bm = (size_t)blockIdx.y * 128;
    const int bn = blockIdx.x * 128;
    const int nit = K0P / 64;    // 10

    float acc[4][4][4];
#pragma unroll
    for (int i = 0; i < 4; i++)
#pragma unroll
        for (int j = 0; j < 4; j++)
#pragma unroll
            for (int v = 0; v < 4; v++) acc[i][j][v] = 0.f;

    l0_load(sb, X, bm, 0, tid);
    l0_load(sb + 2 * L0_AST, Bt, bn, 0, tid);
    CP_COMMIT();
    l0_load(sb + L0_AST, X, bm, 64, tid);
    l0_load(sb + 3 * L0_AST, Bt, bn, 64, tid);
    CP_COMMIT();

    const int rw = lane & 7;
    const int jq = lane >> 3;
    const int a_r = wm * 64 + rw + (jq & 1) * 8;
    const int a_c = jq >> 1;
    const int b_r = wn * 32 + rw + (jq >> 1) * 8;
    const int b_c = jq & 1;

    for (int it = 0; it < nit; it++) {
        if (it + 1 < nit) { CP_WAIT(1); } else { CP_WAIT(0); }
        __syncthreads();
        uint32_t abase = sb + (it & 1) * L0_AST;
        uint32_t bbase = sb + 2 * L0_AST + (it & 1) * L0_AST;
#pragma unroll
        for (int ks = 0; ks < 4; ks++) {
            int cb = ks * 2;
            uint32_t afr[4][4];
#pragma unroll
            for (int mt = 0; mt < 4; mt++)
                ldsm4(afr[mt], abase + swzo(a_r + mt * 16, cb + a_c));
            uint32_t bfr[2][4];
#pragma unroll
            for (int gg = 0; gg < 2; gg++)
                ldsm4(bfr[gg], bbase + swzo(b_r + gg * 16, cb + b_c));
#pragma unroll
            for (int mt = 0; mt < 4; mt++)
#pragma unroll
                for (int nt = 0; nt < 4; nt++)
                    mma_f16(acc[mt][nt], afr[mt], &bfr[nt >> 1][(nt & 1) * 2]);
        }
        __syncthreads();
        if (it + 2 < nit) {
            l0_load(sb + (it & 1) * L0_AST, X, bm, (it + 2) * 64, tid);
            l0_load(sb + (2 + (it & 1)) * L0_AST, Bt, bn, (it + 2) * 64, tid);
            CP_COMMIT();
        }
    }

    const int er = lane >> 2;
    const int ec = (lane & 3) * 2;
#pragma unroll
    for (int mt = 0; mt < 4; mt++) {
#pragma unroll
        for (int nt = 0; nt < 4; nt++) {
            int n = bn + wn * 32 + nt * 8 + ec;
            float bi0 = __ldg(&bias[n]);
            float bi1 = __ldg(&bias[n + 1]);
            size_t m0 = bm + wm * 64 + mt * 16 + er;
            *reinterpret_cast<float2*>(&C[m0 * 256 + n]) =
                make_float2(acc[mt][nt][0] + bi0, acc[mt][nt][1] + bi1);
            *reinterpret_cast<float2*>(&C[(m0 + 8) * 256 + n]) =
                make_float2(acc[mt][nt][2] + bi0, acc[mt][nt][3] + bi1);
        }
    }
}

// ---------------------------------------------------------------------------
// Corner geometry (proven)
// ---------------------------------------------------------------------------
__device__ __forceinline__ void corner_calc(float c0, float c1, int cc,
                                            int& idx, float& rel0, float& rel1) {
    const float rr = 1.0f / 128.0f;
    float vx = (cc & 2) ? 1.f : -1.f;
    float vy = (cc & 1) ? 1.f : -1.f;
    float cy = fminf(fmaxf(c0 + vx * rr + 1e-6f, -1.f + 1e-6f), 1.f - 1e-6f);
    float cx = fminf(fmaxf(c1 + vy * rr + 1e-6f, -1.f + 1e-6f), 1.f - 1e-6f);
    int iy = (int)rintf(((cy + 1.0f) * 128.0f - 1.0f) * 0.5f);
    int ix = (int)rintf(((cx + 1.0f) * 128.0f - 1.0f) * 0.5f);
    iy = min(max(iy, 0), 127);
    ix = min(max(ix, 0), 127);
    float qy = -1.0f + (2.0f * (float)iy + 1.0f) / 128.0f;
    float qx = -1.0f + (2.0f * (float)ix + 1.0f) / 128.0f;
    rel0 = (c0 - qy) * 128.0f;
    rel1 = (c1 - qx) * 128.0f;
    idx = iy * 128 + ix;
}

// ---------------------------------------------------------------------------
// fp16 megakernel (R14-proven, + B prefetch hoisting):
// BM=64 samples/CTA, BN=256, 256 threads, 2 CTAs/SM.
// h (64x256 f16) in 4 swizzled 8KB panels. B: BK=64, 2-stage x 32KB.
// Warps 2(m) x 4(n), warp tile 32x64. Final layer fused.
// ---------------------------------------------------------------------------
#define HP_AST 8192
#define HPN 4
#define MKF_B_BASE (HPN * HP_AST)             // 32768
#define MKF_B_STG  32768
#define MKF_IDX    (MKF_B_BASE + 2 * MKF_B_STG)  // 98304
#define SMEM_MKF   (MKF_IDX + 768)            // 99072
#define MK_T 256

__device__ __forceinline__ void mkf_load_B(uint32_t sb, const __half* __restrict__ Bt,
                                           int k0, int stg, int tid) {
    uint32_t bb = sb + MKF_B_BASE + stg * MKF_B_STG;
#pragma unroll
    for (int i = 0; i < 8; i++) {
        int li = tid + i * MK_T;
        int n = li >> 3, c = li & 7;
        cp16(bb + swzo(n, c), Bt + (size_t)n * 256 + k0 + c * 8);
    }
}

__global__ __launch_bounds__(MK_T, 2) void mk_layers(const float* __restrict__ hr,
                                                     const float* __restrict__ W0,
                                                     const __half* __restrict__ Bt1,
                                                     const float* __restrict__ b1,
                                                     const __half* __restrict__ Bt2,
                                                     const float* __restrict__ b2,
                                                     const __half* __restrict__ Bt3,
                                                     const float* __restrict__ b3,
                                                     const float* __restrict__ W4) {
    extern __shared__ char smem[];
    uint32_t sb = smem_u32(smem);
    int*   sIdx = (int*)(smem + MKF_IDX);
    float* sR0  = (float*)(smem + MKF_IDX + 256);
    float* sR1  = (float*)(smem + MKF_IDX + 512);

    const int tid = threadIdx.x;
    const int wid = tid >> 5, lane = tid & 31;
    const int wm = wid >> 2;
    const int wn = wid & 3;
    const size_t bm = (size_t)blockIdx.x * 64;
    const int er = lane >> 2;
    const int ec = (lane & 3) * 2;

    if (tid < 64) {
        size_t s = bm + tid;
        int cc = (int)(s >> 16);
        int q  = (int)(s & 65535);
        float c0 = hr[2 * q], c1 = hr[2 * q + 1];
        int idx; float r0, r1;
        corner_calc(c0, c1, cc, idx, r0, r1);
        sIdx[tid] = idx; sR0[tid] = r0; sR1[tid] = r1;
    }
    __syncthreads();

    // prefetch layer-1 B chunks 0,1 (independent of the fill below)
    mkf_load_B(sb, Bt1, 0, 0, tid);  CP_COMMIT();
    mkf_load_B(sb, Bt1, 64, 1, tid); CP_COMMIT();

    // ---- fill h(f16) = h16(relu(hp[idx] + r0*W0[585] + r1*W0[586])) ----
#pragma unroll
    for (int p = 0; p < HPN; p++) {
#pragma unroll
        for (int i = 0; i < 2; i++) {
            int li = tid + i * MK_T;
            int m = li >> 3, c = li & 7;
            int k = p * 64 + c * 8;
            int row = sIdx[m];
            float r0 = sR0[m], r1 = sR1[m];
            float4 h0  = __ldg((const float4*)&g_hp[(size_t)row * 256 + k]);
            float4 h1  = __ldg((const float4*)&g_hp[(size_t)row * 256 + k + 4]);
            float4 wa0 = __ldg((const float4*)&W0[585 * 256 + k]);
            float4 wa1 = __ldg((const float4*)&W0[585 * 256 + k + 4]);
            float4 wb0 = __ldg((const float4*)&W0[586 * 256 + k]);
            float4 wb1 = __ldg((const float4*)&W0[586 * 256 + k + 4]);
            __half2 x0 = __floats2half2_rn(fmaxf(h0.x + r0 * wa0.x + r1 * wb0.x, 0.f),
                                           fmaxf(h0.y + r0 * wa0.y + r1 * wb0.y, 0.f));
            __half2 x1 = __floats2half2_rn(fmaxf(h0.z + r0 * wa0.z + r1 * wb0.z, 0.f),
                                           fmaxf(h0.w + r0 * wa0.w + r1 * wb0.w, 0.f));
            __half2 x2 = __floats2half2_rn(fmaxf(h1.x + r0 * wa1.x + r1 * wb1.x, 0.f),
                                           fmaxf(h1.y + r0 * wa1.y + r1 * wb1.y, 0.f));
            __half2 x3 = __floats2half2_rn(fmaxf(h1.z + r0 * wa1.z + r1 * wb1.z, 0.f),
                                           fmaxf(h1.w + r0 * wa1.w + r1 * wb1.w, 0.f));
            uint4 o;
            o.x = *reinterpret_cast<uint32_t*>(&x0);
            o.y = *reinterpret_cast<uint32_t*>(&x1);
            o.z = *reinterpret_cast<uint32_t*>(&x2);
            o.w = *reinterpret_cast<uint32_t*>(&x3);
            *reinterpret_cast<uint4*>(smem + p * HP_AST + swzo(m, c)) = o;
        }
    }
    __syncthreads();

    const int rw = lane & 7;
    const int jq = lane >> 3;
    const int a_r = wm * 32 + rw + (jq & 1) * 8;
    const int a_c = jq >> 1;
    const int b_r = wn * 64 + rw + (jq >> 1) * 8;
    const int b_c = jq & 1;

    const __half* Bts[3]   = {Bt1, Bt2, Bt3};
    const float* biases[3] = {b1, b2, b3};

#pragma unroll 1
    for (int L = 0; L < 3; L++) {
        const __half* Bt = Bts[L];
        const float* bias = biases[L];

        float acc[2][8][4];
#pragma unroll
        for (int i = 0; i < 2; i++)
#pragma unroll
            for (int j = 0; j < 8; j++)
#pragma unroll
                for (int v = 0; v < 4; v++) acc[i][j][v] = 0.f;

        // chunks 0,1 already in flight (prologue or previous epilogue prefetch)
#pragma unroll 1
        for (int it = 0; it < 4; it++) {
            if (it + 1 < 4) { CP_WAIT(1); } else { CP_WAIT(0); }
            __syncthreads();
            uint32_t abase = sb + it * HP_AST;
            uint32_t bbase = sb + MKF_B_BASE + (it & 1) * MKF_B_STG;
#pragma unroll
            for (int ks = 0; ks < 4; ks++) {
                int cb = ks * 2;
                uint32_t afr[2][4];
#pragma unroll
                for (int mt = 0; mt < 2; mt++)
                    ldsm4(afr[mt], abase + swzo(a_r + mt * 16, cb + a_c));
                uint32_t bfr[4][4];
#pragma unroll
                for (int gg = 0; gg < 4; gg++)
                    ldsm4(bfr[gg], bbase + swzo(b_r + gg * 16, cb + b_c));
#pragma unroll
                for (int mt = 0; mt < 2; mt++)
#pragma unroll
                    for (int nt = 0; nt < 8; nt++)
                        mma_f16(acc[mt][nt], afr[mt], &bfr[nt >> 1][(nt & 1) * 2]);
            }
            __syncthreads();
            if (it + 2 < 4) {
                mkf_load_B(sb, Bt, (it + 2) * 64, it & 1, tid);
                CP_COMMIT();
            }
        }

        // prefetch next layer's chunks 0,1 (stages free; overlaps epilogue+fill)
        if (L < 2) {
            mkf_load_B(sb, Bts[L + 1], 0, 0, tid);  CP_COMMIT();
            mkf_load_B(sb, Bts[L + 1], 64, 1, tid); CP_COMMIT();
        }

        if (L < 2) {
            // write acc -> h panels (f16) with bias+relu
#pragma unroll
            for (int mt = 0; mt < 2; mt++) {
#pragma unroll
                for (int nt = 0; nt < 8; nt++) {
                    int n = wn * 64 + nt * 8 + ec;
                    float bi0 = __ldg(&bias[n]);
                    float bi1 = __ldg(&bias[n + 1]);
                    int r0 = wm * 32 + mt * 16 + er;
                    int r1 = r0 + 8;
                    __half2 lo = __floats2half2_rn(fmaxf(acc[mt][nt][0] + bi0, 0.f),
                                                   fmaxf(acc[mt][nt][1] + bi1, 0.f));
                    __half2 hi = __floats2half2_rn(fmaxf(acc[mt][nt][2] + bi0, 0.f),
                                                   fmaxf(acc[mt][nt][3] + bi1, 0.f));
                    int panel = n >> 6;
                    int chunk = (n & 63) >> 3;
                    int sub = (n & 7) * 2;
                    *reinterpret_cast<__half2*>(smem + panel * HP_AST +
                                                swzo(r0, chunk) + sub) = lo;
                    *reinterpret_cast<__half2*>(smem + panel * HP_AST +
                                                swzo(r1, chunk) + sub) = hi;
                }
            }
            __syncthreads();
        } else {
            // fused final layer: h4 = relu(acc + b3); dot with W4 (__ldg); atomics
#pragma unroll
            for (int mt = 0; mt < 2; mt++) {
                float p[2][3];
#pragma unroll
                for (int h = 0; h < 2; h++)
#pragma unroll
                    for (int c = 0; c < 3; c++) p[h][c] = 0.f;
#pragma unroll
                for (int nt = 0; nt < 8; nt++) {
                    int n = wn * 64 + nt * 8 + ec;
                    float bi0 = __ldg(&bias[n]);
                    float bi1 = __ldg(&bias[n + 1]);
                    float v0 = fmaxf(acc[mt][nt][0] + bi0, 0.f);
                    float v1 = fmaxf(acc[mt][nt][1] + bi1, 0.f);
                    float v2 = fmaxf(acc[mt][nt][2] + bi0, 0.f);
                    float v3 = fmaxf(acc[mt][nt][3] + bi1, 0.f);
#pragma unroll
                    for (int c = 0; c < 3; c++) {
                        float w0 = __ldg(&W4[n * 3 + c]);
                        float w1 = __ldg(&W4[(n + 1) * 3 + c]);
                        p[0][c] += v0 * w0 + v1 * w1;
                        p[1][c] += v2 * w0 + v3 * w1;
                    }
                }
#pragma unroll
                for (int h = 0; h < 2; h++)
#pragma unroll
                    for (int c = 0; c < 3; c++) {
                        p[h][c] += __shfl_xor_sync(0xFFFFFFFFu, p[h][c], 1);
                        p[h][c] += __shfl_xor_sync(0xFFFFFFFFu, p[h][c], 2);
                    }
                if ((lane & 3) == 0) {
                    size_t m0 = bm + wm * 32 + mt * 16 + er;
#pragma unroll
                    for (int c = 0; c < 3; c++) {
                        atomicAdd(&g_pred[m0 * 3 + c],       p[0][c]);
                        atomicAdd(&g_pred[(m0 + 8) * 3 + c], p[1][c]);
                    }
                }
            }
        }
    }
}

// ---------------------------------------------------------------------------
// im2col (padded to 640, fp16)
// ---------------------------------------------------------------------------
__global__ void build_X(const float* __restrict__ mf, const float* __restrict__ mask) {
    int p = blockIdx.x;
    int t = threadIdx.x;
    if (t >= K0P) return;
    int y = p >> 7, x = p & 127;
    float v = 0.f;
    if (t < K1) {
        int c = t / 9, r = t - c * 9;
        int ki = r / 3, kj = r - ki * 3;
        int yy = y + ki - 1, xx = x + kj - 1;
        if (yy >= 0 && yy < FH && xx >= 0 && xx < FW) {
            v = (c < 64) ? mf[(c << 14) + (yy << 7) + xx] : mask[(yy << 7) + xx];
        }
    }
    g_Xh[p * K0P + t] = __float2half_rn(v);
}

// ---------------------------------------------------------------------------
// Merged prep: Wth0..3 (fp16 transposed) + zero g_pred
// ---------------------------------------------------------------------------
#define SEG0 (256 * K0P)
#define SEG1 (256 * 256)
#define PREP_TOT (SEG0 + 3 * SEG1 + SN * 3)
__global__ void prep_all(const float* __restrict__ W0, const float* __restrict__ W1,
                         const float* __restrict__ W2, const float* __restrict__ W3) {
    int i = blockIdx.x * blockDim.x + threadIdx.x;
    if (i >= PREP_TOT) return;
    if (i < SEG0) {
        int n = i / K0P, k = i - n * K0P;
        g_Wth0[i] = __float2half_rn((k < K1) ? W0[k * 256 + n] : 0.f);
        return;
    }
    i -= SEG0;
    if (i < SEG1) { int n = i >> 8, k = i & 255; g_Wth1[i] = __float2half_rn(W1[k * 256 + n]); return; }
    i -= SEG1;
    if (i < SEG1) { int n = i >> 8, k = i & 255; g_Wth2[i] = __float2half_rn(W2[k * 256 + n]); return; }
    i -= SEG1;
    if (i < SEG1) { int n = i >> 8, k = i & 255; g_Wth3[i] = __float2half_rn(W3[k * 256 + n]); return; }
    i -= SEG1;
    g_pred[i] = 0.f;
}

// ---------------------------------------------------------------------------
// local ensemble (adds b4)
// ---------------------------------------------------------------------------
__global__ void ensemble(const float* __restrict__ hr, const float* __restrict__ b4,
                         float* __restrict__ out) {
    int q = blockIdx.x * blockDim.x + threadIdx.x;
    if (q >= QN) return;
    float c0 = hr[2 * q], c1 = hr[2 * q + 1];
    float b40 = __ldg(&b4[0]), b41 = __ldg(&b4[1]), b42 = __ldg(&b4[2]);
    float area[4];
#pragma unroll
    for (int cc = 0; cc < 4; cc++) {
        int idx; float r0, r1;
        corner_calc(c0, c1, cc, idx, r0, r1);
        area[cc] = fabsf(r0 * r1) + 1e-9f;
    }
    float tot = area[0] + area[1] + area[2] + area[3];
    float o0 = 0.f, o1 = 0.f, o2 = 0.f;
#pragma unroll
    for (int cc = 0; cc < 4; cc++) {
        float w = area[3 - cc] / tot;
        size_t s = (size_t)cc * QN + q;
        o0 += (g_pred[s * 3 + 0] + b40) * w;
        o1 += (g_pred[s * 3 + 1] + b41) * w;
        o2 += (g_pred[s * 3 + 2] + b42) * w;
    }
    out[0 * QN + q] = o0;
    out[1 * QN + q] = o1;
    out[2 * QN + q] = o2;
}

// ---------------------------------------------------------------------------
// Launch
// ---------------------------------------------------------------------------
extern "C" void kernel_launch(void* const* d_in, const int* in_sizes, int n_in,
                              void* d_out, int out_size) {
    const float* mf   = (const float*)d_in[0];
    const float* mask = (const float*)d_in[1];
    const float* hr = (const float*)d_in[3];
    const float* W0 = (const float*)d_in[4];
    const float* b0 = (const float*)d_in[5];
    const float* W1 = (const float*)d_in[6];
    const float* b1 = (const float*)d_in[7];
    const float* W2 = (const float*)d_in[8];
    const float* b2 = (const float*)d_in[9];
    const float* W3 = (const float*)d_in[10];
    const float* b3 = (const float*)d_in[11];
    const float* W4 = (const float*)d_in[12];
    const float* b4 = (const float*)d_in[13];
    float* out = (float*)d_out;

    void *pX, *pW0, *pW1, *pW2, *pW3, *pHp;
    cudaGetSymbolAddress(&pX,  g_Xh);
    cudaGetSymbolAddress(&pW0, g_Wth0);
    cudaGetSymbolAddress(&pW1, g_Wth1);
    cudaGetSymbolAddress(&pW2, g_Wth2);
    cudaGetSymbolAddress(&pW3, g_Wth3);
    cudaGetSymbolAddress(&pHp, g_hp);

    cudaFuncSetAttribute(gemm_l0,   cudaFuncAttributeMaxDynamicSharedMemorySize, SMEM_L0);
    cudaFuncSetAttribute(mk_layers, cudaFuncAttributeMaxDynamicSharedMemorySize, SMEM_MKF);

    build_X<<<NPIX, K0P>>>(mf, mask);
    prep_all<<<(PREP_TOT + 255) / 256, 256>>>(W0, W1, W2, W3);

    // hp = X @ W0 + b0 (fp16 mainloop, fp32 out)
    gemm_l0<<<dim3(2, NPIX / 128), 256, SMEM_L0>>>((const __half*)pX, (const __half*)pW0,
                                                   b0, (float*)pHp);

    // layers 1-3 fused, fp16 (BM=64, 256 threads, 2 CTAs/SM, B prefetch hoisted)
    mk_layers<<<SN / 64, MK_T, SMEM_MKF>>>(hr, W0,
                                           (const __half*)pW1, b1,
                                           (const __half*)pW2, b2,
                                           (const __half*)pW3, b3, W4);

    ensemble<<<QN / 256, 256>>>(hr, b4, out);
}